// round 1
// baseline (speedup 1.0000x reference)
#include <cuda_runtime.h>

// Problem constants
// B=4, H=W=128, C=256, heads=8, d=32, win=16 -> 256 windows x 256 tokens
// Scratch: q,k,v in [win][head][tok][d]; o in (B,H,W,C) row-major.
__device__ float g_q[16777216];
__device__ float g_k[16777216];
__device__ float g_v[16777216];
__device__ float g_o[16777216];

// ---------------------------------------------------------------------------
// Kernel 1: q = (x_wsa @ q_w + q_b) * (1/sqrt(32)), scattered into window layout
// GEMM M=65536 N=256 K=256, 64x64 tiles, 4x4 micro-tiles
// ---------------------------------------------------------------------------
__global__ __launch_bounds__(256) void qproj_kernel(const float* __restrict__ X,
                                                    const float* __restrict__ Wm,
                                                    const float* __restrict__ bias) {
    __shared__ __align__(16) float As[16][64];
    __shared__ __align__(16) float Bs[16][64];
    const int tid = threadIdx.x;
    const int m0 = blockIdx.x * 64;
    const int n0 = blockIdx.y * 64;
    const int lr = tid >> 2, lk = (tid & 3) * 4;
    const int br = tid >> 4, bc = (tid & 15) * 4;
    const int ty = tid >> 4, tx = tid & 15;
    float acc[4][4] = {};
    for (int k0 = 0; k0 < 256; k0 += 16) {
        float4 a = *(const float4*)(X + (m0 + lr) * 256 + k0 + lk);
        As[lk + 0][lr] = a.x; As[lk + 1][lr] = a.y;
        As[lk + 2][lr] = a.z; As[lk + 3][lr] = a.w;
        *(float4*)&Bs[br][bc] = *(const float4*)(Wm + (k0 + br) * 256 + n0 + bc);
        __syncthreads();
#pragma unroll
        for (int kk = 0; kk < 16; kk++) {
            float4 av = *(const float4*)&As[kk][ty * 4];
            float4 bv = *(const float4*)&Bs[kk][tx * 4];
            acc[0][0] += av.x * bv.x; acc[0][1] += av.x * bv.y; acc[0][2] += av.x * bv.z; acc[0][3] += av.x * bv.w;
            acc[1][0] += av.y * bv.x; acc[1][1] += av.y * bv.y; acc[1][2] += av.y * bv.z; acc[1][3] += av.y * bv.w;
            acc[2][0] += av.z * bv.x; acc[2][1] += av.z * bv.y; acc[2][2] += av.z * bv.z; acc[2][3] += av.z * bv.w;
            acc[3][0] += av.w * bv.x; acc[3][1] += av.w * bv.y; acc[3][2] += av.w * bv.z; acc[3][3] += av.w * bv.w;
        }
        __syncthreads();
    }
    const float scale = 0.17677669529663687f;  // 1/sqrt(32)
#pragma unroll
    for (int i = 0; i < 4; i++) {
        int m = m0 + ty * 4 + i;
        int b = m >> 14, rem = m & 16383;
        int r = rem >> 7, c = rem & 127;
        int n = b * 64 + (r >> 4) * 8 + (c >> 4);
        int t = (r & 15) * 16 + (c & 15);
#pragma unroll
        for (int j = 0; j < 4; j++) {
            int col = n0 + tx * 4 + j;
            float v = (acc[i][j] + bias[col]) * scale;
            g_q[((n * 8 + (col >> 5)) * 256 + t) * 32 + (col & 31)] = v;
        }
    }
}

// ---------------------------------------------------------------------------
// Kernel 2: grouped 5x5 conv (pad 2, groups=8): kv = conv(x_original) + kv_b
// oc<256 -> K, oc>=256 -> V, scattered into window layout.
// Block = (batch b, group g, 16x16 spatial tile, 16-oc chunk). 256 threads.
// smem: input planes [ic][20][20] (8 ic per chunk), weights [25][8][16].
// ---------------------------------------------------------------------------
__global__ __launch_bounds__(256) void convkv_kernel(const float* __restrict__ X,
                                                     const float* __restrict__ Wc,
                                                     const float* __restrict__ bias) {
    __shared__ __align__(16) float patch[8 * 400];  // [ic][py*20+px]
    __shared__ __align__(16) float wsm[3200];       // [(kk*8+ic)*16+o]
    const int tid = threadIdx.x;
    const int tile = blockIdx.x;
    const int ty0 = (tile >> 3) * 16, tx0 = (tile & 7) * 16;
    const int b = blockIdx.y >> 3, g = blockIdx.y & 7;
    const int och = blockIdx.z;
    const int sy = tid >> 4, sx = tid & 15;
    float acc[16] = {};
#pragma unroll 1
    for (int c4 = 0; c4 < 4; c4++) {   // ic chunks of 8
        __syncthreads();
        for (int p = tid; p < 400; p += 256) {
            int py = p / 20, px = p - py * 20;
            int gy = ty0 + py - 2, gx = tx0 + px - 2;
            float4 v0 = make_float4(0.f, 0.f, 0.f, 0.f);
            float4 v1 = make_float4(0.f, 0.f, 0.f, 0.f);
            if (gy >= 0 && gy < 128 && gx >= 0 && gx < 128) {
                const float4* src = (const float4*)(X + ((b * 128 + gy) * 128 + gx) * 256 + g * 32 + c4 * 8);
                v0 = src[0]; v1 = src[1];
            }
            patch[0 * 400 + p] = v0.x; patch[1 * 400 + p] = v0.y;
            patch[2 * 400 + p] = v0.z; patch[3 * 400 + p] = v0.w;
            patch[4 * 400 + p] = v1.x; patch[5 * 400 + p] = v1.y;
            patch[6 * 400 + p] = v1.z; patch[7 * 400 + p] = v1.w;
        }
        for (int idx = tid; idx < 3200; idx += 256) {
            int o = idx & 15;
            int rest = idx >> 4;
            int ic = rest & 7;
            int kk = rest >> 3;
            wsm[idx] = Wc[(kk * 32 + c4 * 8 + ic) * 512 + g * 64 + och * 16 + o];
        }
        __syncthreads();
#pragma unroll 1
        for (int ky = 0; ky < 5; ky++) {
#pragma unroll
            for (int kx = 0; kx < 5; kx++) {
                const int pbase = (sy + ky) * 20 + (sx + kx);
                const float* wp = wsm + (ky * 5 + kx) * 128;
#pragma unroll
                for (int ic = 0; ic < 8; ic++) {
                    float xv = patch[ic * 400 + pbase];
                    const float4* w4 = (const float4*)(wp + ic * 16);
                    float4 w0 = w4[0], w1 = w4[1], w2 = w4[2], w3 = w4[3];
                    acc[0]  += xv * w0.x; acc[1]  += xv * w0.y; acc[2]  += xv * w0.z; acc[3]  += xv * w0.w;
                    acc[4]  += xv * w1.x; acc[5]  += xv * w1.y; acc[6]  += xv * w1.z; acc[7]  += xv * w1.w;
                    acc[8]  += xv * w2.x; acc[9]  += xv * w2.y; acc[10] += xv * w2.z; acc[11] += xv * w2.w;
                    acc[12] += xv * w3.x; acc[13] += xv * w3.y; acc[14] += xv * w3.z; acc[15] += xv * w3.w;
                }
            }
        }
    }
    const int ocbase = g * 64 + och * 16;
    const int y = ty0 + sy, x = tx0 + sx;
    const int n = b * 64 + (y >> 4) * 8 + (x >> 4);
    const int t = (y & 15) * 16 + (x & 15);
    float* dst = (ocbase < 256) ? g_k : g_v;
    const int j0 = ocbase & 255;
    const int addr = ((n * 8 + (j0 >> 5)) * 256 + t) * 32 + (j0 & 31);
#pragma unroll
    for (int o4 = 0; o4 < 4; o4++) {
        float4 v;
        v.x = acc[o4 * 4 + 0] + bias[ocbase + o4 * 4 + 0];
        v.y = acc[o4 * 4 + 1] + bias[ocbase + o4 * 4 + 1];
        v.z = acc[o4 * 4 + 2] + bias[ocbase + o4 * 4 + 2];
        v.w = acc[o4 * 4 + 3] + bias[ocbase + o4 * 4 + 3];
        *(float4*)&dst[addr + o4 * 4] = v;
    }
}

// ---------------------------------------------------------------------------
// Kernel 3: windowed attention, one block per (window, head). Flash-style
// online softmax; k/v streamed through smem in 16-row chunks; bias per head
// cached in smem. Writes o back into (B,H,W,C) row-major scratch.
// ---------------------------------------------------------------------------
__global__ __launch_bounds__(256, 2) void attn_kernel(const float* __restrict__ bias_table) {
    const int n = blockIdx.x, hd = blockIdx.y;
    const int t = threadIdx.x;
    __shared__ __align__(16) float ks[16 * 32];
    __shared__ __align__(16) float vs[16 * 32];
    __shared__ float bs[961];
    for (int i = t; i < 961; i += 256) bs[i] = bias_table[i * 8 + hd];
    const float* qp = g_q + ((n * 8 + hd) * 256 + t) * 32;
    float q[32];
#pragma unroll
    for (int d4 = 0; d4 < 8; d4++) {
        float4 v = *(const float4*)(qp + d4 * 4);
        q[d4 * 4 + 0] = v.x; q[d4 * 4 + 1] = v.y; q[d4 * 4 + 2] = v.z; q[d4 * 4 + 3] = v.w;
    }
    float o[32] = {};
    float mrun = -1e30f, l = 0.f;
    const int ty = t >> 4, tx = t & 15;
    const float* kb = g_k + (n * 8 + hd) * 256 * 32;
    const float* vb = g_v + (n * 8 + hd) * 256 * 32;
#pragma unroll 1
    for (int sb = 0; sb < 16; sb++) {   // 16 key chunks of 16 tokens
        __syncthreads();
        if (t < 128) *(float4*)&ks[t * 4] = *(const float4*)(kb + sb * 512 + t * 4);
        else         *(float4*)&vs[(t - 128) * 4] = *(const float4*)(vb + sb * 512 + (t - 128) * 4);
        __syncthreads();
        float sc[16];
#pragma unroll
        for (int j = 0; j < 16; j++) {
            float a = 0.f;
#pragma unroll
            for (int d4 = 0; d4 < 8; d4++) {
                float4 kv4 = *(const float4*)&ks[j * 32 + d4 * 4];
                a += q[d4 * 4 + 0] * kv4.x + q[d4 * 4 + 1] * kv4.y
                   + q[d4 * 4 + 2] * kv4.z + q[d4 * 4 + 3] * kv4.w;
            }
            // key token s = sb*16 + j  ->  sy = sb, sx = j
            sc[j] = a + bs[(ty - sb + 15) * 31 + (tx - j + 15)];
        }
        float mb = mrun;
#pragma unroll
        for (int j = 0; j < 16; j++) mb = fmaxf(mb, sc[j]);
        float corr = __expf(mrun - mb);
        l *= corr;
#pragma unroll
        for (int dd = 0; dd < 32; dd++) o[dd] *= corr;
#pragma unroll
        for (int j = 0; j < 16; j++) {
            float p = __expf(sc[j] - mb);
            l += p;
#pragma unroll
            for (int d4 = 0; d4 < 8; d4++) {
                float4 vv = *(const float4*)&vs[j * 32 + d4 * 4];
                o[d4 * 4 + 0] += p * vv.x;
                o[d4 * 4 + 1] += p * vv.y;
                o[d4 * 4 + 2] += p * vv.z;
                o[d4 * 4 + 3] += p * vv.w;
            }
        }
        mrun = mb;
    }
    const float inv = 1.f / l;
    const int bimg = n >> 6, wh = (n >> 3) & 7, ww = n & 7;
    const int r = wh * 16 + ty, c = ww * 16 + tx;
    float* op = g_o + ((bimg * 128 + r) * 128 + c) * 256 + hd * 32;
#pragma unroll
    for (int d4 = 0; d4 < 8; d4++) {
        float4 v = make_float4(o[d4 * 4 + 0] * inv, o[d4 * 4 + 1] * inv,
                               o[d4 * 4 + 2] * inv, o[d4 * 4 + 3] * inv);
        *(float4*)(op + d4 * 4) = v;
    }
}

// ---------------------------------------------------------------------------
// Kernel 4: out = rezero * (o @ out_w + out_b)
// ---------------------------------------------------------------------------
__global__ __launch_bounds__(256) void outproj_kernel(const float* __restrict__ Wm,
                                                      const float* __restrict__ bias,
                                                      const float* __restrict__ rz,
                                                      float* __restrict__ out) {
    __shared__ __align__(16) float As[16][64];
    __shared__ __align__(16) float Bs[16][64];
    const int tid = threadIdx.x;
    const int m0 = blockIdx.x * 64;
    const int n0 = blockIdx.y * 64;
    const int lr = tid >> 2, lk = (tid & 3) * 4;
    const int br = tid >> 4, bc = (tid & 15) * 4;
    const int ty = tid >> 4, tx = tid & 15;
    float acc[4][4] = {};
    for (int k0 = 0; k0 < 256; k0 += 16) {
        float4 a = *(const float4*)(g_o + (m0 + lr) * 256 + k0 + lk);
        As[lk + 0][lr] = a.x; As[lk + 1][lr] = a.y;
        As[lk + 2][lr] = a.z; As[lk + 3][lr] = a.w;
        *(float4*)&Bs[br][bc] = *(const float4*)(Wm + (k0 + br) * 256 + n0 + bc);
        __syncthreads();
#pragma unroll
        for (int kk = 0; kk < 16; kk++) {
            float4 av = *(const float4*)&As[kk][ty * 4];
            float4 bv = *(const float4*)&Bs[kk][tx * 4];
            acc[0][0] += av.x * bv.x; acc[0][1] += av.x * bv.y; acc[0][2] += av.x * bv.z; acc[0][3] += av.x * bv.w;
            acc[1][0] += av.y * bv.x; acc[1][1] += av.y * bv.y; acc[1][2] += av.y * bv.z; acc[1][3] += av.y * bv.w;
            acc[2][0] += av.z * bv.x; acc[2][1] += av.z * bv.y; acc[2][2] += av.z * bv.z; acc[2][3] += av.z * bv.w;
            acc[3][0] += av.w * bv.x; acc[3][1] += av.w * bv.y; acc[3][2] += av.w * bv.z; acc[3][3] += av.w * bv.w;
        }
        __syncthreads();
    }
    const float r = rz[0];
#pragma unroll
    for (int i = 0; i < 4; i++) {
        int m = m0 + ty * 4 + i;
        float4 v;
        v.x = r * (acc[i][0] + bias[n0 + tx * 4 + 0]);
        v.y = r * (acc[i][1] + bias[n0 + tx * 4 + 1]);
        v.z = r * (acc[i][2] + bias[n0 + tx * 4 + 2]);
        v.w = r * (acc[i][3] + bias[n0 + tx * 4 + 3]);
        *(float4*)&out[m * 256 + n0 + tx * 4] = v;
    }
}

// ---------------------------------------------------------------------------
extern "C" void kernel_launch(void* const* d_in, const int* in_sizes, int n_in,
                              void* d_out, int out_size) {
    (void)in_sizes; (void)n_in; (void)out_size;
    const float* x_wsa      = (const float*)d_in[0];
    const float* x_original = (const float*)d_in[1];
    const float* q_w        = (const float*)d_in[2];
    const float* q_b        = (const float*)d_in[3];
    const float* kv_w       = (const float*)d_in[4];
    const float* kv_b       = (const float*)d_in[5];
    const float* out_w      = (const float*)d_in[6];
    const float* out_b      = (const float*)d_in[7];
    const float* bias_table = (const float*)d_in[8];
    const float* rezero     = (const float*)d_in[9];
    float* out = (float*)d_out;

    qproj_kernel<<<dim3(1024, 4), 256>>>(x_wsa, q_w, q_b);
    convkv_kernel<<<dim3(64, 32, 4), 256>>>(x_original, kv_w, kv_b);
    attn_kernel<<<dim3(256, 8), 256>>>(bias_table);
    outproj_kernel<<<dim3(1024, 4), 256>>>(out_w, out_b, rezero, out);
}

// round 3
// speedup vs baseline: 2.6555x; 2.6555x over previous
#include <cuda_runtime.h>

// B=4, H=W=128, C=256, heads=8, d=32, win=16 -> 256 windows x 256 tokens
__device__ float g_q[16777216];
__device__ float g_k[16777216];
__device__ float g_v[16777216];
__device__ float g_o[16777216];

__device__ __forceinline__ float to_tf32(float x) {
    unsigned u;
    asm("cvt.rna.tf32.f32 %0, %1;" : "=r"(u) : "f"(x));
    return __uint_as_float(u);
}

__device__ __forceinline__ void mma_tf32(float* c, const unsigned* a, const unsigned* b) {
    asm volatile(
        "mma.sync.aligned.m16n8k8.row.col.f32.tf32.tf32.f32 "
        "{%0,%1,%2,%3},{%4,%5,%6,%7},{%8,%9},{%0,%1,%2,%3};"
        : "+f"(c[0]), "+f"(c[1]), "+f"(c[2]), "+f"(c[3])
        : "r"(a[0]), "r"(a[1]), "r"(a[2]), "r"(a[3]), "r"(b[0]), "r"(b[1]));
}

// ---------------------------------------------------------------------------
// Conv 5x5 grouped (pad 2, groups=8) as implicit GEMM on tensor cores.
// Block = (b, g, 16x16 tile): M=256 pixels, N=64 oc, K=25 taps x 32 ic.
// ---------------------------------------------------------------------------
#define CONV_PATCH_FL 14400   // 20*20*36
#define CONV_WBUF_FL  2304    // 32*72
#define CONV_SMEM_B   ((CONV_PATCH_FL + 2*CONV_WBUF_FL) * 4)

__global__ __launch_bounds__(256, 2) void convkv_mma(const float* __restrict__ X,
                                                     const float* __restrict__ Wc,
                                                     const float* __restrict__ bias) {
    extern __shared__ float smem[];
    float* patch = smem;
    float* wsm = smem + CONV_PATCH_FL;

    const int tid = threadIdx.x;
    const int lane = tid & 31, warp = tid >> 5;
    const int wm = warp & 3, wn = warp >> 2;
    const int tile = blockIdx.x;
    const int ty0 = (tile >> 3) * 16, tx0 = (tile & 7) * 16;
    const int b = blockIdx.y >> 3, g = blockIdx.y & 7;

    // Load 20x20x32 input patch (zero-padded), converted to tf32
    for (int p = tid; p < 400; p += 256) {
        int py = p / 20, px = p - py * 20;
        int gy = ty0 + py - 2, gx = tx0 + px - 2;
        bool ok = (gy >= 0 && gy < 128 && gx >= 0 && gx < 128);
        const float4* src = (const float4*)(X + ((b * 128 + gy) * 128 + gx) * 256 + g * 32);
#pragma unroll
        for (int c8 = 0; c8 < 8; c8++) {
            float4 v = ok ? src[c8] : make_float4(0.f, 0.f, 0.f, 0.f);
            float4 w = make_float4(to_tf32(v.x), to_tf32(v.y), to_tf32(v.z), to_tf32(v.w));
            *(float4*)&patch[p * 36 + c8 * 4] = w;
        }
    }

    const int wic = tid >> 3, woc = (tid & 7) * 8;
    {   // tap 0 -> buf 0
        const float4* gp = (const float4*)(Wc + (0 * 32 + wic) * 512 + g * 64 + woc);
        float4 r0 = gp[0], r1 = gp[1];
        float* dw = wsm + wic * 72 + woc;
        *(float4*)dw = make_float4(to_tf32(r0.x), to_tf32(r0.y), to_tf32(r0.z), to_tf32(r0.w));
        *(float4*)(dw + 4) = make_float4(to_tf32(r1.x), to_tf32(r1.y), to_tf32(r1.z), to_tf32(r1.w));
    }
    __syncthreads();

    float acc[4][4][4] = {};

#pragma unroll 1
    for (int tap = 0; tap < 25; tap++) {
        const int ky = tap / 5, kx = tap - ky * 5;
        float4 r0, r1;
        if (tap < 24) {
            const float4* gp = (const float4*)(Wc + ((tap + 1) * 32 + wic) * 512 + g * 64 + woc);
            r0 = gp[0]; r1 = gp[1];
        }
        const float* wcur = wsm + (tap & 1) * CONV_WBUF_FL;
#pragma unroll
        for (int kc = 0; kc < 4; kc++) {
            unsigned a[4][4];
#pragma unroll
            for (int i = 0; i < 4; i++) {
                const int base = ((wm * 4 + i + ky) * 20 + kx) * 36 + kc * 8;
                const int o0 = base + (lane >> 2) * 36 + (lane & 3);
                a[i][0] = __float_as_uint(patch[o0]);
                a[i][1] = __float_as_uint(patch[o0 + 8 * 36]);
                a[i][2] = __float_as_uint(patch[o0 + 4]);
                a[i][3] = __float_as_uint(patch[o0 + 8 * 36 + 4]);
            }
#pragma unroll
            for (int j = 0; j < 4; j++) {
                const int nn = wn * 32 + j * 8 + (lane >> 2);
                unsigned bf[2];
                bf[0] = __float_as_uint(wcur[(kc * 8 + (lane & 3)) * 72 + nn]);
                bf[1] = __float_as_uint(wcur[(kc * 8 + (lane & 3) + 4) * 72 + nn]);
#pragma unroll
                for (int i = 0; i < 4; i++) mma_tf32(acc[i][j], a[i], bf);
            }
        }
        if (tap < 24) {
            float* dw = wsm + ((tap + 1) & 1) * CONV_WBUF_FL + wic * 72 + woc;
            *(float4*)dw = make_float4(to_tf32(r0.x), to_tf32(r0.y), to_tf32(r0.z), to_tf32(r0.w));
            *(float4*)(dw + 4) = make_float4(to_tf32(r1.x), to_tf32(r1.y), to_tf32(r1.z), to_tf32(r1.w));
        }
        __syncthreads();
    }

    // Epilogue: add bias, scatter into window layout of g_k / g_v
    const int win = b * 64 + (tile >> 3) * 8 + (tile & 7);
    const int head = (g & 3) * 2 + wn;
    float* dst = (g < 4) ? g_k : g_v;
    float* base = dst + ((win * 8 + head) * 256) * 32;
#pragma unroll
    for (int i = 0; i < 4; i++) {
        const int p0 = wm * 64 + i * 16 + (lane >> 2);
#pragma unroll
        for (int j = 0; j < 4; j++) {
            const int col = wn * 32 + j * 8 + (lane & 3) * 2;
            const int d = col & 31;
            float b0 = bias[g * 64 + col], b1 = bias[g * 64 + col + 1];
            *(float2*)(base + p0 * 32 + d) = make_float2(acc[i][j][0] + b0, acc[i][j][1] + b1);
            *(float2*)(base + (p0 + 8) * 32 + d) = make_float2(acc[i][j][2] + b0, acc[i][j][3] + b1);
        }
    }
}

// ---------------------------------------------------------------------------
// tf32 GEMM: M=65536, N=256, K=256. Block 128M x 64N, warp 32x32.
// MODE 0: qproj A=param (x_wsa), scatter to g_q with scale.
// MODE 1: outproj A=g_o (device symbol! host cannot pass its address), -> out.
// ---------------------------------------------------------------------------
#define GEMM_ABUF_FL 4608    // 128*36
#define GEMM_BBUF_FL 2304    // 32*72
#define GEMM_SMEM_B  ((2*GEMM_ABUF_FL + 2*GEMM_BBUF_FL) * 4)

template <int MODE>
__global__ __launch_bounds__(256, 2) void gemm_mma(const float* __restrict__ Aparam,
                                                   const float* __restrict__ Wm,
                                                   const float* __restrict__ bias,
                                                   const float* __restrict__ rz,
                                                   float* __restrict__ out) {
    extern __shared__ float smem[];
    float* as = smem;                       // 2 x [128][36]
    float* bs = smem + 2 * GEMM_ABUF_FL;    // 2 x [32][72]

    // Select A source in DEVICE code: g_o's address is only valid device-side.
    const float* A = (MODE == 1) ? (const float*)g_o : Aparam;

    const int tid = threadIdx.x;
    const int lane = tid & 31, warp = tid >> 5;
    const int wm = warp & 3, wn = warp >> 2;
    const int m0 = blockIdx.x * 128;
    const int n0 = blockIdx.y * 64;

    const int arow = tid >> 1, akoff = (tid & 1) * 16;
    const int wic = tid >> 3, woc = (tid & 7) * 8;

    {   // chunk 0 -> buf 0
        const float4* ga = (const float4*)(A + (m0 + arow) * 256 + akoff);
        float* da = as + arow * 36 + akoff;
#pragma unroll
        for (int c4 = 0; c4 < 4; c4++) {
            float4 v = ga[c4];
            *(float4*)(da + c4 * 4) = make_float4(to_tf32(v.x), to_tf32(v.y), to_tf32(v.z), to_tf32(v.w));
        }
        const float4* gb = (const float4*)(Wm + wic * 256 + n0 + woc);
        float4 r0 = gb[0], r1 = gb[1];
        float* db = bs + wic * 72 + woc;
        *(float4*)db = make_float4(to_tf32(r0.x), to_tf32(r0.y), to_tf32(r0.z), to_tf32(r0.w));
        *(float4*)(db + 4) = make_float4(to_tf32(r1.x), to_tf32(r1.y), to_tf32(r1.z), to_tf32(r1.w));
    }
    __syncthreads();

    float acc[2][4][4] = {};

#pragma unroll 1
    for (int kt = 0; kt < 8; kt++) {
        float4 pa[4], pb0, pb1;
        if (kt < 7) {
            const float4* ga = (const float4*)(A + (m0 + arow) * 256 + (kt + 1) * 32 + akoff);
#pragma unroll
            for (int c4 = 0; c4 < 4; c4++) pa[c4] = ga[c4];
            const float4* gb = (const float4*)(Wm + ((kt + 1) * 32 + wic) * 256 + n0 + woc);
            pb0 = gb[0]; pb1 = gb[1];
        }
        const float* acur = as + (kt & 1) * GEMM_ABUF_FL;
        const float* bcur = bs + (kt & 1) * GEMM_BBUF_FL;
#pragma unroll
        for (int kc = 0; kc < 4; kc++) {
            unsigned a[2][4];
#pragma unroll
            for (int i = 0; i < 2; i++) {
                const int o0 = (wm * 32 + i * 16 + (lane >> 2)) * 36 + kc * 8 + (lane & 3);
                a[i][0] = __float_as_uint(acur[o0]);
                a[i][1] = __float_as_uint(acur[o0 + 8 * 36]);
                a[i][2] = __float_as_uint(acur[o0 + 4]);
                a[i][3] = __float_as_uint(acur[o0 + 8 * 36 + 4]);
            }
#pragma unroll
            for (int j = 0; j < 4; j++) {
                const int nn = wn * 32 + j * 8 + (lane >> 2);
                unsigned bf[2];
                bf[0] = __float_as_uint(bcur[(kc * 8 + (lane & 3)) * 72 + nn]);
                bf[1] = __float_as_uint(bcur[(kc * 8 + (lane & 3) + 4) * 72 + nn]);
#pragma unroll
                for (int i = 0; i < 2; i++) mma_tf32(acc[i][j], a[i], bf);
            }
        }
        if (kt < 7) {
            float* da = as + ((kt + 1) & 1) * GEMM_ABUF_FL + arow * 36 + akoff;
#pragma unroll
            for (int c4 = 0; c4 < 4; c4++)
                *(float4*)(da + c4 * 4) = make_float4(to_tf32(pa[c4].x), to_tf32(pa[c4].y),
                                                      to_tf32(pa[c4].z), to_tf32(pa[c4].w));
            float* db = bs + ((kt + 1) & 1) * GEMM_BBUF_FL + wic * 72 + woc;
            *(float4*)db = make_float4(to_tf32(pb0.x), to_tf32(pb0.y), to_tf32(pb0.z), to_tf32(pb0.w));
            *(float4*)(db + 4) = make_float4(to_tf32(pb1.x), to_tf32(pb1.y), to_tf32(pb1.z), to_tf32(pb1.w));
        }
        __syncthreads();
    }

    const float scale = 0.17677669529663687f;  // 1/sqrt(32)
    const float r = (MODE == 1) ? rz[0] : 0.f;
#pragma unroll
    for (int i = 0; i < 2; i++) {
        const int m = m0 + wm * 32 + i * 16 + (lane >> 2);
#pragma unroll
        for (int j = 0; j < 4; j++) {
            const int col = n0 + wn * 32 + j * 8 + (lane & 3) * 2;
            const float b0 = bias[col], b1 = bias[col + 1];
            if (MODE == 0) {
                const int bi = m >> 14, rr = (m >> 7) & 127, cc = m & 127;
                const int win = bi * 64 + ((rr >> 4) << 3) + (cc >> 4);
                const int t = (rr & 15) * 16 + (cc & 15);
                const int head = col >> 5, d = col & 31;
                float* p = g_q + ((win * 8 + head) * 256 + t) * 32 + d;
                *(float2*)p = make_float2((acc[i][j][0] + b0) * scale, (acc[i][j][1] + b1) * scale);
                *(float2*)(p + 8 * 32) = make_float2((acc[i][j][2] + b0) * scale, (acc[i][j][3] + b1) * scale);
            } else {
                float* p = out + m * 256 + col;
                *(float2*)p = make_float2(r * (acc[i][j][0] + b0), r * (acc[i][j][1] + b1));
                *(float2*)(p + 8 * 256) = make_float2(r * (acc[i][j][2] + b0), r * (acc[i][j][3] + b1));
            }
        }
    }
}

// ---------------------------------------------------------------------------
// Kernel 3: windowed attention (unchanged)
// ---------------------------------------------------------------------------
__global__ __launch_bounds__(256, 2) void attn_kernel(const float* __restrict__ bias_table) {
    const int n = blockIdx.x, hd = blockIdx.y;
    const int t = threadIdx.x;
    __shared__ __align__(16) float ks[16 * 32];
    __shared__ __align__(16) float vs[16 * 32];
    __shared__ float bs[961];
    for (int i = t; i < 961; i += 256) bs[i] = bias_table[i * 8 + hd];
    const float* qp = g_q + ((n * 8 + hd) * 256 + t) * 32;
    float q[32];
#pragma unroll
    for (int d4 = 0; d4 < 8; d4++) {
        float4 v = *(const float4*)(qp + d4 * 4);
        q[d4 * 4 + 0] = v.x; q[d4 * 4 + 1] = v.y; q[d4 * 4 + 2] = v.z; q[d4 * 4 + 3] = v.w;
    }
    float o[32] = {};
    float mrun = -1e30f, l = 0.f;
    const int ty = t >> 4, tx = t & 15;
    const float* kb = g_k + (n * 8 + hd) * 256 * 32;
    const float* vb = g_v + (n * 8 + hd) * 256 * 32;
#pragma unroll 1
    for (int sb = 0; sb < 16; sb++) {
        __syncthreads();
        if (t < 128) *(float4*)&ks[t * 4] = *(const float4*)(kb + sb * 512 + t * 4);
        else         *(float4*)&vs[(t - 128) * 4] = *(const float4*)(vb + sb * 512 + (t - 128) * 4);
        __syncthreads();
        float sc[16];
#pragma unroll
        for (int j = 0; j < 16; j++) {
            float a = 0.f;
#pragma unroll
            for (int d4 = 0; d4 < 8; d4++) {
                float4 kv4 = *(const float4*)&ks[j * 32 + d4 * 4];
                a += q[d4 * 4 + 0] * kv4.x + q[d4 * 4 + 1] * kv4.y
                   + q[d4 * 4 + 2] * kv4.z + q[d4 * 4 + 3] * kv4.w;
            }
            sc[j] = a + bs[(ty - sb + 15) * 31 + (tx - j + 15)];
        }
        float mb = mrun;
#pragma unroll
        for (int j = 0; j < 16; j++) mb = fmaxf(mb, sc[j]);
        float corr = __expf(mrun - mb);
        l *= corr;
#pragma unroll
        for (int dd = 0; dd < 32; dd++) o[dd] *= corr;
#pragma unroll
        for (int j = 0; j < 16; j++) {
            float p = __expf(sc[j] - mb);
            l += p;
#pragma unroll
            for (int d4 = 0; d4 < 8; d4++) {
                float4 vv = *(const float4*)&vs[j * 32 + d4 * 4];
                o[d4 * 4 + 0] += p * vv.x;
                o[d4 * 4 + 1] += p * vv.y;
                o[d4 * 4 + 2] += p * vv.z;
                o[d4 * 4 + 3] += p * vv.w;
            }
        }
        mrun = mb;
    }
    const float inv = 1.f / l;
    const int bimg = n >> 6, wh = (n >> 3) & 7, ww = n & 7;
    const int r = wh * 16 + ty, c = ww * 16 + tx;
    float* op = g_o + ((bimg * 128 + r) * 128 + c) * 256 + hd * 32;
#pragma unroll
    for (int d4 = 0; d4 < 8; d4++) {
        float4 v = make_float4(o[d4 * 4 + 0] * inv, o[d4 * 4 + 1] * inv,
                               o[d4 * 4 + 2] * inv, o[d4 * 4 + 3] * inv);
        *(float4*)(op + d4 * 4) = v;
    }
}

// ---------------------------------------------------------------------------
extern "C" void kernel_launch(void* const* d_in, const int* in_sizes, int n_in,
                              void* d_out, int out_size) {
    (void)in_sizes; (void)n_in; (void)out_size;
    const float* x_wsa      = (const float*)d_in[0];
    const float* x_original = (const float*)d_in[1];
    const float* q_w        = (const float*)d_in[2];
    const float* q_b        = (const float*)d_in[3];
    const float* kv_w       = (const float*)d_in[4];
    const float* kv_b       = (const float*)d_in[5];
    const float* out_w      = (const float*)d_in[6];
    const float* out_b      = (const float*)d_in[7];
    const float* bias_table = (const float*)d_in[8];
    const float* rezero     = (const float*)d_in[9];
    float* out = (float*)d_out;

    cudaFuncSetAttribute(convkv_mma, cudaFuncAttributeMaxDynamicSharedMemorySize, CONV_SMEM_B);
    cudaFuncSetAttribute(gemm_mma<0>, cudaFuncAttributeMaxDynamicSharedMemorySize, GEMM_SMEM_B);
    cudaFuncSetAttribute(gemm_mma<1>, cudaFuncAttributeMaxDynamicSharedMemorySize, GEMM_SMEM_B);

    gemm_mma<0><<<dim3(512, 4), 256, GEMM_SMEM_B>>>(x_wsa, q_w, q_b, nullptr, nullptr);
    convkv_mma<<<dim3(64, 32), 256, CONV_SMEM_B>>>(x_original, kv_w, kv_b);
    attn_kernel<<<dim3(256, 8), 256>>>(bias_table);
    gemm_mma<1><<<dim3(512, 4), 256, GEMM_SMEM_B>>>(nullptr, out_w, out_b, rezero, out);
}

// round 4
// speedup vs baseline: 3.6111x; 1.3599x over previous
#include <cuda_runtime.h>

// B=4, H=W=128, C=256, heads=8, d=32, win=16 -> 256 windows x 256 tokens
__device__ float g_q[16777216];
__device__ float g_k[16777216];
__device__ float g_v[16777216];
__device__ float g_o[16777216];
__device__ float g_bias[524288];   // [head][256 q][256 k]

__device__ __forceinline__ float to_tf32(float x) {
    unsigned u;
    asm("cvt.rna.tf32.f32 %0, %1;" : "=r"(u) : "f"(x));
    return __uint_as_float(u);
}

__device__ __forceinline__ void mma_tf32(float* c, const unsigned* a, const unsigned* b) {
    asm volatile(
        "mma.sync.aligned.m16n8k8.row.col.f32.tf32.tf32.f32 "
        "{%0,%1,%2,%3},{%4,%5,%6,%7},{%8,%9},{%0,%1,%2,%3};"
        : "+f"(c[0]), "+f"(c[1]), "+f"(c[2]), "+f"(c[3])
        : "r"(a[0]), "r"(a[1]), "r"(a[2]), "r"(a[3]), "r"(b[0]), "r"(b[1]));
}

// ---------------------------------------------------------------------------
// Bias expansion: g_bias[hd][q][k] = bias_table[rel_index(q,k)][hd]
// ---------------------------------------------------------------------------
__global__ void bias_expand(const float* __restrict__ bt) {
    const int kt = threadIdx.x, qt = blockIdx.x, hd = blockIdx.y;
    const int qy = qt >> 4, qx = qt & 15, ky = kt >> 4, kx = kt & 15;
    const int rel = (qy - ky + 15) * 31 + (qx - kx + 15);
    g_bias[(hd << 16) + (qt << 8) + kt] = bt[rel * 8 + hd];
}

// ---------------------------------------------------------------------------
// Conv 5x5 grouped (pad 2, groups=8) as implicit GEMM on tensor cores.
// ---------------------------------------------------------------------------
#define CONV_PATCH_FL 14400   // 20*20*36
#define CONV_WBUF_FL  2304    // 32*72
#define CONV_SMEM_B   ((CONV_PATCH_FL + 2*CONV_WBUF_FL) * 4)

__global__ __launch_bounds__(256, 2) void convkv_mma(const float* __restrict__ X,
                                                     const float* __restrict__ Wc,
                                                     const float* __restrict__ bias) {
    extern __shared__ float smem[];
    float* patch = smem;
    float* wsm = smem + CONV_PATCH_FL;

    const int tid = threadIdx.x;
    const int lane = tid & 31, warp = tid >> 5;
    const int wm = warp & 3, wn = warp >> 2;
    const int tile = blockIdx.x;
    const int ty0 = (tile >> 3) * 16, tx0 = (tile & 7) * 16;
    const int b = blockIdx.y >> 3, g = blockIdx.y & 7;

    for (int p = tid; p < 400; p += 256) {
        int py = p / 20, px = p - py * 20;
        int gy = ty0 + py - 2, gx = tx0 + px - 2;
        bool ok = (gy >= 0 && gy < 128 && gx >= 0 && gx < 128);
        const float4* src = (const float4*)(X + ((b * 128 + gy) * 128 + gx) * 256 + g * 32);
#pragma unroll
        for (int c8 = 0; c8 < 8; c8++) {
            float4 v = ok ? src[c8] : make_float4(0.f, 0.f, 0.f, 0.f);
            float4 w = make_float4(to_tf32(v.x), to_tf32(v.y), to_tf32(v.z), to_tf32(v.w));
            *(float4*)&patch[p * 36 + c8 * 4] = w;
        }
    }

    const int wic = tid >> 3, woc = (tid & 7) * 8;
    {
        const float4* gp = (const float4*)(Wc + (0 * 32 + wic) * 512 + g * 64 + woc);
        float4 r0 = gp[0], r1 = gp[1];
        float* dw = wsm + wic * 72 + woc;
        *(float4*)dw = make_float4(to_tf32(r0.x), to_tf32(r0.y), to_tf32(r0.z), to_tf32(r0.w));
        *(float4*)(dw + 4) = make_float4(to_tf32(r1.x), to_tf32(r1.y), to_tf32(r1.z), to_tf32(r1.w));
    }
    __syncthreads();

    float acc[4][4][4] = {};

#pragma unroll 1
    for (int tap = 0; tap < 25; tap++) {
        const int ky = tap / 5, kx = tap - ky * 5;
        float4 r0, r1;
        if (tap < 24) {
            const float4* gp = (const float4*)(Wc + ((tap + 1) * 32 + wic) * 512 + g * 64 + woc);
            r0 = gp[0]; r1 = gp[1];
        }
        const float* wcur = wsm + (tap & 1) * CONV_WBUF_FL;
#pragma unroll
        for (int kc = 0; kc < 4; kc++) {
            unsigned a[4][4];
#pragma unroll
            for (int i = 0; i < 4; i++) {
                const int base = ((wm * 4 + i + ky) * 20 + kx) * 36 + kc * 8;
                const int o0 = base + (lane >> 2) * 36 + (lane & 3);
                a[i][0] = __float_as_uint(patch[o0]);
                a[i][1] = __float_as_uint(patch[o0 + 8 * 36]);
                a[i][2] = __float_as_uint(patch[o0 + 4]);
                a[i][3] = __float_as_uint(patch[o0 + 8 * 36 + 4]);
            }
#pragma unroll
            for (int j = 0; j < 4; j++) {
                const int nn = wn * 32 + j * 8 + (lane >> 2);
                unsigned bf[2];
                bf[0] = __float_as_uint(wcur[(kc * 8 + (lane & 3)) * 72 + nn]);
                bf[1] = __float_as_uint(wcur[(kc * 8 + (lane & 3) + 4) * 72 + nn]);
#pragma unroll
                for (int i = 0; i < 4; i++) mma_tf32(acc[i][j], a[i], bf);
            }
        }
        if (tap < 24) {
            float* dw = wsm + ((tap + 1) & 1) * CONV_WBUF_FL + wic * 72 + woc;
            *(float4*)dw = make_float4(to_tf32(r0.x), to_tf32(r0.y), to_tf32(r0.z), to_tf32(r0.w));
            *(float4*)(dw + 4) = make_float4(to_tf32(r1.x), to_tf32(r1.y), to_tf32(r1.z), to_tf32(r1.w));
        }
        __syncthreads();
    }

    // Epilogue: bias, round to tf32 (attention consumes via mma), scatter
    const int win = b * 64 + (tile >> 3) * 8 + (tile & 7);
    const int head = (g & 3) * 2 + wn;
    float* dst = (g < 4) ? g_k : g_v;
    float* base = dst + ((win * 8 + head) * 256) * 32;
#pragma unroll
    for (int i = 0; i < 4; i++) {
        const int p0 = wm * 64 + i * 16 + (lane >> 2);
#pragma unroll
        for (int j = 0; j < 4; j++) {
            const int col = wn * 32 + j * 8 + (lane & 3) * 2;
            const int d = col & 31;
            float b0 = bias[g * 64 + col], b1 = bias[g * 64 + col + 1];
            *(float2*)(base + p0 * 32 + d) =
                make_float2(to_tf32(acc[i][j][0] + b0), to_tf32(acc[i][j][1] + b1));
            *(float2*)(base + (p0 + 8) * 32 + d) =
                make_float2(to_tf32(acc[i][j][2] + b0), to_tf32(acc[i][j][3] + b1));
        }
    }
}

// ---------------------------------------------------------------------------
// tf32 GEMM: MODE 0 qproj (-> g_q, tf32-rounded), MODE 1 outproj (g_o -> out)
// ---------------------------------------------------------------------------
#define GEMM_ABUF_FL 4608    // 128*36
#define GEMM_BBUF_FL 2304    // 32*72
#define GEMM_SMEM_B  ((2*GEMM_ABUF_FL + 2*GEMM_BBUF_FL) * 4)

template <int MODE>
__global__ __launch_bounds__(256, 2) void gemm_mma(const float* __restrict__ Aparam,
                                                   const float* __restrict__ Wm,
                                                   const float* __restrict__ bias,
                                                   const float* __restrict__ rz,
                                                   float* __restrict__ out) {
    extern __shared__ float smem[];
    float* as = smem;
    float* bs = smem + 2 * GEMM_ABUF_FL;

    const float* A = (MODE == 1) ? (const float*)g_o : Aparam;

    const int tid = threadIdx.x;
    const int lane = tid & 31, warp = tid >> 5;
    const int wm = warp & 3, wn = warp >> 2;
    const int m0 = blockIdx.x * 128;
    const int n0 = blockIdx.y * 64;

    const int arow = tid >> 1, akoff = (tid & 1) * 16;
    const int wic = tid >> 3, woc = (tid & 7) * 8;

    {
        const float4* ga = (const float4*)(A + (m0 + arow) * 256 + akoff);
        float* da = as + arow * 36 + akoff;
#pragma unroll
        for (int c4 = 0; c4 < 4; c4++) {
            float4 v = ga[c4];
            *(float4*)(da + c4 * 4) = make_float4(to_tf32(v.x), to_tf32(v.y), to_tf32(v.z), to_tf32(v.w));
        }
        const float4* gb = (const float4*)(Wm + wic * 256 + n0 + woc);
        float4 r0 = gb[0], r1 = gb[1];
        float* db = bs + wic * 72 + woc;
        *(float4*)db = make_float4(to_tf32(r0.x), to_tf32(r0.y), to_tf32(r0.z), to_tf32(r0.w));
        *(float4*)(db + 4) = make_float4(to_tf32(r1.x), to_tf32(r1.y), to_tf32(r1.z), to_tf32(r1.w));
    }
    __syncthreads();

    float acc[2][4][4] = {};

#pragma unroll 1
    for (int kt = 0; kt < 8; kt++) {
        float4 pa[4], pb0, pb1;
        if (kt < 7) {
            const float4* ga = (const float4*)(A + (m0 + arow) * 256 + (kt + 1) * 32 + akoff);
#pragma unroll
            for (int c4 = 0; c4 < 4; c4++) pa[c4] = ga[c4];
            const float4* gb = (const float4*)(Wm + ((kt + 1) * 32 + wic) * 256 + n0 + woc);
            pb0 = gb[0]; pb1 = gb[1];
        }
        const float* acur = as + (kt & 1) * GEMM_ABUF_FL;
        const float* bcur = bs + (kt & 1) * GEMM_BBUF_FL;
#pragma unroll
        for (int kc = 0; kc < 4; kc++) {
            unsigned a[2][4];
#pragma unroll
            for (int i = 0; i < 2; i++) {
                const int o0 = (wm * 32 + i * 16 + (lane >> 2)) * 36 + kc * 8 + (lane & 3);
                a[i][0] = __float_as_uint(acur[o0]);
                a[i][1] = __float_as_uint(acur[o0 + 8 * 36]);
                a[i][2] = __float_as_uint(acur[o0 + 4]);
                a[i][3] = __float_as_uint(acur[o0 + 8 * 36 + 4]);
            }
#pragma unroll
            for (int j = 0; j < 4; j++) {
                const int nn = wn * 32 + j * 8 + (lane >> 2);
                unsigned bf[2];
                bf[0] = __float_as_uint(bcur[(kc * 8 + (lane & 3)) * 72 + nn]);
                bf[1] = __float_as_uint(bcur[(kc * 8 + (lane & 3) + 4) * 72 + nn]);
#pragma unroll
                for (int i = 0; i < 2; i++) mma_tf32(acc[i][j], a[i], bf);
            }
        }
        if (kt < 7) {
            float* da = as + ((kt + 1) & 1) * GEMM_ABUF_FL + arow * 36 + akoff;
#pragma unroll
            for (int c4 = 0; c4 < 4; c4++)
                *(float4*)(da + c4 * 4) = make_float4(to_tf32(pa[c4].x), to_tf32(pa[c4].y),
                                                      to_tf32(pa[c4].z), to_tf32(pa[c4].w));
            float* db = bs + ((kt + 1) & 1) * GEMM_BBUF_FL + wic * 72 + woc;
            *(float4*)db = make_float4(to_tf32(pb0.x), to_tf32(pb0.y), to_tf32(pb0.z), to_tf32(pb0.w));
            *(float4*)(db + 4) = make_float4(to_tf32(pb1.x), to_tf32(pb1.y), to_tf32(pb1.z), to_tf32(pb1.w));
        }
        __syncthreads();
    }

    const float scale = 0.17677669529663687f;
    const float r = (MODE == 1) ? rz[0] : 0.f;
#pragma unroll
    for (int i = 0; i < 2; i++) {
        const int m = m0 + wm * 32 + i * 16 + (lane >> 2);
#pragma unroll
        for (int j = 0; j < 4; j++) {
            const int col = n0 + wn * 32 + j * 8 + (lane & 3) * 2;
            const float b0 = bias[col], b1 = bias[col + 1];
            if (MODE == 0) {
                const int bi = m >> 14, rr = (m >> 7) & 127, cc = m & 127;
                const int win = bi * 64 + ((rr >> 4) << 3) + (cc >> 4);
                const int t = (rr & 15) * 16 + (cc & 15);
                const int head = col >> 5, d = col & 31;
                float* p = g_q + ((win * 8 + head) * 256 + t) * 32 + d;
                *(float2*)p = make_float2(to_tf32((acc[i][j][0] + b0) * scale),
                                          to_tf32((acc[i][j][1] + b1) * scale));
                *(float2*)(p + 8 * 32) = make_float2(to_tf32((acc[i][j][2] + b0) * scale),
                                                     to_tf32((acc[i][j][3] + b1) * scale));
            } else {
                float* p = out + m * 256 + col;
                *(float2*)p = make_float2(r * (acc[i][j][0] + b0), r * (acc[i][j][1] + b1));
                *(float2*)(p + 8 * 256) = make_float2(r * (acc[i][j][2] + b0), r * (acc[i][j][3] + b1));
            }
        }
    }
}

// ---------------------------------------------------------------------------
// Tensor-core flash attention. Block = (window, head), 8 warps; warp owns
// 32 query rows. KV streamed in 64-key chunks with register prefetch.
// Q/K smem pitch 36 (bank = 4q+t conflict-free), V pitch 40 (bank = 8k+q).
// P converted C-frag -> A-frag via quad shuffles (no smem round-trip).
// ---------------------------------------------------------------------------
#define ATT_QS 9216   // 256*36
#define ATT_KS 2304   // 64*36
#define ATT_VS 2560   // 64*40
#define ATT_SMEM_B ((ATT_QS + ATT_KS + ATT_VS) * 4)

__global__ __launch_bounds__(256, 1) void attn_mma() {
    extern __shared__ float sm[];
    float* Qs = sm;
    float* Ks = sm + ATT_QS;
    float* Vs = sm + ATT_QS + ATT_KS;

    const int win = blockIdx.x, hd = blockIdx.y;
    const int tid = threadIdx.x;
    const int lane = tid & 31, warp = tid >> 5;
    const int q = lane >> 2, t = lane & 3;
    const int wb = warp * 32;

    const float* qb = g_q + (win * 8 + hd) * 8192;
    const float* kb = g_k + (win * 8 + hd) * 8192;
    const float* vb = g_v + (win * 8 + hd) * 8192;
    const float* bb = g_bias + (hd << 16);

    // Stage Q (persistent) and chunk 0 of K/V
    for (int i = tid; i < 2048; i += 256) {
        float4 v = ((const float4*)qb)[i];
        *(float4*)&Qs[(i >> 3) * 36 + (i & 7) * 4] = v;
    }
    {
        float4 k0 = ((const float4*)kb)[tid], k1 = ((const float4*)kb)[tid + 256];
        float4 v0 = ((const float4*)vb)[tid], v1 = ((const float4*)vb)[tid + 256];
        *(float4*)&Ks[(tid >> 3) * 36 + (tid & 7) * 4] = k0;
        *(float4*)&Ks[((tid + 256) >> 3) * 36 + (tid & 7) * 4] = k1;
        *(float4*)&Vs[(tid >> 3) * 40 + (tid & 7) * 4] = v0;
        *(float4*)&Vs[((tid + 256) >> 3) * 40 + (tid & 7) * 4] = v1;
    }
    __syncthreads();

    float o[2][4][4] = {};
    float mrow[2][2] = {{-1e30f, -1e30f}, {-1e30f, -1e30f}};
    float lrow[2][2] = {};

    const int src = (q << 2) + (t >> 1);
    const int srcHi = src + 2;
    const bool odd = t & 1;

#pragma unroll 1
    for (int sb = 0; sb < 4; sb++) {
        // prefetch next chunk into registers
        float4 kn0, kn1, vn0, vn1;
        if (sb < 3) {
            const float4* knp = (const float4*)(kb + (sb + 1) * 2048);
            const float4* vnp = (const float4*)(vb + (sb + 1) * 2048);
            kn0 = knp[tid]; kn1 = knp[tid + 256];
            vn0 = vnp[tid]; vn1 = vnp[tid + 256];
        }

        // S = Q K^T for this warp's 32 rows x 64 keys
        float s[2][8][4] = {};
#pragma unroll
        for (int kc = 0; kc < 4; kc++) {
            unsigned qa[2][4];
#pragma unroll
            for (int mt = 0; mt < 2; mt++) {
                const int o0 = (wb + mt * 16 + q) * 36 + kc * 8 + t;
                qa[mt][0] = __float_as_uint(Qs[o0]);
                qa[mt][1] = __float_as_uint(Qs[o0 + 8 * 36]);
                qa[mt][2] = __float_as_uint(Qs[o0 + 4]);
                qa[mt][3] = __float_as_uint(Qs[o0 + 8 * 36 + 4]);
            }
#pragma unroll
            for (int nt = 0; nt < 8; nt++) {
                const int ba = (nt * 8 + q) * 36 + kc * 8 + t;
                unsigned bf[2];
                bf[0] = __float_as_uint(Ks[ba]);
                bf[1] = __float_as_uint(Ks[ba + 4]);
                mma_tf32(s[0][nt], qa[0], bf);
                mma_tf32(s[1][nt], qa[1], bf);
            }
        }

        // bias add + online softmax
#pragma unroll
        for (int mt = 0; mt < 2; mt++) {
            const int r0 = wb + mt * 16 + q;
#pragma unroll
            for (int nt = 0; nt < 8; nt++) {
                const int c0 = sb * 64 + nt * 8 + t * 2;
                float2 bv0 = *(const float2*)&bb[r0 * 256 + c0];
                float2 bv1 = *(const float2*)&bb[(r0 + 8) * 256 + c0];
                s[mt][nt][0] += bv0.x; s[mt][nt][1] += bv0.y;
                s[mt][nt][2] += bv1.x; s[mt][nt][3] += bv1.y;
            }
            float mx0 = -1e30f, mx1 = -1e30f;
#pragma unroll
            for (int nt = 0; nt < 8; nt++) {
                mx0 = fmaxf(mx0, fmaxf(s[mt][nt][0], s[mt][nt][1]));
                mx1 = fmaxf(mx1, fmaxf(s[mt][nt][2], s[mt][nt][3]));
            }
            mx0 = fmaxf(mx0, __shfl_xor_sync(0xffffffff, mx0, 1));
            mx0 = fmaxf(mx0, __shfl_xor_sync(0xffffffff, mx0, 2));
            mx1 = fmaxf(mx1, __shfl_xor_sync(0xffffffff, mx1, 1));
            mx1 = fmaxf(mx1, __shfl_xor_sync(0xffffffff, mx1, 2));
            const float mn0 = fmaxf(mrow[mt][0], mx0);
            const float mn1 = fmaxf(mrow[mt][1], mx1);
            const float cor0 = __expf(mrow[mt][0] - mn0);
            const float cor1 = __expf(mrow[mt][1] - mn1);
            mrow[mt][0] = mn0; mrow[mt][1] = mn1;
#pragma unroll
            for (int dn = 0; dn < 4; dn++) {
                o[mt][dn][0] *= cor0; o[mt][dn][1] *= cor0;
                o[mt][dn][2] *= cor1; o[mt][dn][3] *= cor1;
            }
            float sm0 = 0.f, sm1 = 0.f;
#pragma unroll
            for (int nt = 0; nt < 8; nt++) {
                float p0 = __expf(s[mt][nt][0] - mn0);
                float p1 = __expf(s[mt][nt][1] - mn0);
                float p2 = __expf(s[mt][nt][2] - mn1);
                float p3 = __expf(s[mt][nt][3] - mn1);
                sm0 += p0 + p1; sm1 += p2 + p3;
                s[mt][nt][0] = to_tf32(p0); s[mt][nt][1] = to_tf32(p1);
                s[mt][nt][2] = to_tf32(p2); s[mt][nt][3] = to_tf32(p3);
            }
            sm0 += __shfl_xor_sync(0xffffffff, sm0, 1);
            sm0 += __shfl_xor_sync(0xffffffff, sm0, 2);
            sm1 += __shfl_xor_sync(0xffffffff, sm1, 1);
            sm1 += __shfl_xor_sync(0xffffffff, sm1, 2);
            lrow[mt][0] = lrow[mt][0] * cor0 + sm0;
            lrow[mt][1] = lrow[mt][1] * cor1 + sm1;
        }

        // O += P V : C-frag -> A-frag via quad shuffles
#pragma unroll
        for (int kk = 0; kk < 8; kk++) {
            unsigned pa[2][4];
#pragma unroll
            for (int mt = 0; mt < 2; mt++) {
                float v0 = __shfl_sync(0xffffffff, s[mt][kk][0], src);
                float v1 = __shfl_sync(0xffffffff, s[mt][kk][1], src);
                float v2 = __shfl_sync(0xffffffff, s[mt][kk][2], src);
                float v3 = __shfl_sync(0xffffffff, s[mt][kk][3], src);
                float w0 = __shfl_sync(0xffffffff, s[mt][kk][0], srcHi);
                float w1 = __shfl_sync(0xffffffff, s[mt][kk][1], srcHi);
                float w2 = __shfl_sync(0xffffffff, s[mt][kk][2], srcHi);
                float w3 = __shfl_sync(0xffffffff, s[mt][kk][3], srcHi);
                pa[mt][0] = __float_as_uint(odd ? v1 : v0);
                pa[mt][1] = __float_as_uint(odd ? v3 : v2);
                pa[mt][2] = __float_as_uint(odd ? w1 : w0);
                pa[mt][3] = __float_as_uint(odd ? w3 : w2);
            }
#pragma unroll
            for (int dn = 0; dn < 4; dn++) {
                const int va = (kk * 8 + t) * 40 + dn * 8 + q;
                unsigned bf[2];
                bf[0] = __float_as_uint(Vs[va]);
                bf[1] = __float_as_uint(Vs[va + 4 * 40]);
                mma_tf32(o[0][dn], pa[0], bf);
                mma_tf32(o[1][dn], pa[1], bf);
            }
        }

        __syncthreads();
        if (sb < 3) {
            *(float4*)&Ks[(tid >> 3) * 36 + (tid & 7) * 4] = kn0;
            *(float4*)&Ks[((tid + 256) >> 3) * 36 + (tid & 7) * 4] = kn1;
            *(float4*)&Vs[(tid >> 3) * 40 + (tid & 7) * 4] = vn0;
            *(float4*)&Vs[((tid + 256) >> 3) * 40 + (tid & 7) * 4] = vn1;
        }
        __syncthreads();
    }

    // Epilogue: normalize, write to (B,H,W,C) layout in g_o
    const int bimg = win >> 6, wh = (win >> 3) & 7, ww = win & 7;
#pragma unroll
    for (int mt = 0; mt < 2; mt++) {
        const float inv0 = 1.f / lrow[mt][0];
        const float inv1 = 1.f / lrow[mt][1];
        const int tk0 = wb + mt * 16 + q;
#pragma unroll
        for (int half = 0; half < 2; half++) {
            const int tk = tk0 + half * 8;
            const float inv = half ? inv1 : inv0;
            const int gr = wh * 16 + (tk >> 4), gc = ww * 16 + (tk & 15);
            float* op = g_o + ((bimg * 128 + gr) * 128 + gc) * 256 + hd * 32;
#pragma unroll
            for (int dn = 0; dn < 4; dn++) {
                float a = o[mt][dn][half * 2] * inv;
                float b = o[mt][dn][half * 2 + 1] * inv;
                *(float2*)(op + dn * 8 + t * 2) = make_float2(a, b);
            }
        }
    }
}

// ---------------------------------------------------------------------------
extern "C" void kernel_launch(void* const* d_in, const int* in_sizes, int n_in,
                              void* d_out, int out_size) {
    (void)in_sizes; (void)n_in; (void)out_size;
    const float* x_wsa      = (const float*)d_in[0];
    const float* x_original = (const float*)d_in[1];
    const float* q_w        = (const float*)d_in[2];
    const float* q_b        = (const float*)d_in[3];
    const float* kv_w       = (const float*)d_in[4];
    const float* kv_b       = (const float*)d_in[5];
    const float* out_w      = (const float*)d_in[6];
    const float* out_b      = (const float*)d_in[7];
    const float* bias_table = (const float*)d_in[8];
    const float* rezero     = (const float*)d_in[9];
    float* out = (float*)d_out;

    cudaFuncSetAttribute(convkv_mma, cudaFuncAttributeMaxDynamicSharedMemorySize, CONV_SMEM_B);
    cudaFuncSetAttribute(gemm_mma<0>, cudaFuncAttributeMaxDynamicSharedMemorySize, GEMM_SMEM_B);
    cudaFuncSetAttribute(gemm_mma<1>, cudaFuncAttributeMaxDynamicSharedMemorySize, GEMM_SMEM_B);
    cudaFuncSetAttribute(attn_mma, cudaFuncAttributeMaxDynamicSharedMemorySize, ATT_SMEM_B);

    bias_expand<<<dim3(256, 8), 256>>>(bias_table);
    gemm_mma<0><<<dim3(512, 4), 256, GEMM_SMEM_B>>>(x_wsa, q_w, q_b, nullptr, nullptr);
    convkv_mma<<<dim3(64, 32), 256, CONV_SMEM_B>>>(x_original, kv_w, kv_b);
    attn_mma<<<dim3(256, 8), 256, ATT_SMEM_B>>>();
    gemm_mma<1><<<dim3(512, 4), 256, GEMM_SMEM_B>>>(nullptr, out_w, out_b, rezero, out);
}

// round 5
// speedup vs baseline: 3.7414x; 1.0361x over previous
#include <cuda_runtime.h>

// B=4, H=W=128, C=256, heads=8, d=32, win=16 -> 256 windows x 256 tokens
__device__ float g_q[16777216];
__device__ float g_k[16777216];
__device__ float g_v[16777216];
__device__ float g_o[16777216];
__device__ float g_bias[524288];   // [head][256 q][256 k]

__device__ __forceinline__ float to_tf32(float x) {
    unsigned u;
    asm("cvt.rna.tf32.f32 %0, %1;" : "=r"(u) : "f"(x));
    return __uint_as_float(u);
}

__device__ __forceinline__ void mma_tf32(float* c, const unsigned* a, const unsigned* b) {
    asm volatile(
        "mma.sync.aligned.m16n8k8.row.col.f32.tf32.tf32.f32 "
        "{%0,%1,%2,%3},{%4,%5,%6,%7},{%8,%9},{%0,%1,%2,%3};"
        : "+f"(c[0]), "+f"(c[1]), "+f"(c[2]), "+f"(c[3])
        : "r"(a[0]), "r"(a[1]), "r"(a[2]), "r"(a[3]), "r"(b[0]), "r"(b[1]));
}

// ---------------------------------------------------------------------------
// Bias expansion: g_bias[hd][q][k] = bias_table[rel_index(q,k)][hd]
// ---------------------------------------------------------------------------
__global__ void bias_expand(const float* __restrict__ bt) {
    const int kt = threadIdx.x, qt = blockIdx.x, hd = blockIdx.y;
    const int qy = qt >> 4, qx = qt & 15, ky = kt >> 4, kx = kt & 15;
    const int rel = (qy - ky + 15) * 31 + (qx - kx + 15);
    g_bias[(hd << 16) + (qt << 8) + kt] = bt[rel * 8 + hd];
}

// ---------------------------------------------------------------------------
// Conv 5x5 grouped (pad 2, groups=8) as implicit GEMM on tensor cores.
// ---------------------------------------------------------------------------
#define CONV_PATCH_FL 14400   // 20*20*36
#define CONV_WBUF_FL  2304    // 32*72
#define CONV_SMEM_B   ((CONV_PATCH_FL + 2*CONV_WBUF_FL) * 4)

__global__ __launch_bounds__(256, 2) void convkv_mma(const float* __restrict__ X,
                                                     const float* __restrict__ Wc,
                                                     const float* __restrict__ bias) {
    extern __shared__ float smem[];
    float* patch = smem;
    float* wsm = smem + CONV_PATCH_FL;

    const int tid = threadIdx.x;
    const int lane = tid & 31, warp = tid >> 5;
    const int wm = warp & 3, wn = warp >> 2;
    const int tile = blockIdx.x;
    const int ty0 = (tile >> 3) * 16, tx0 = (tile & 7) * 16;
    const int b = blockIdx.y >> 3, g = blockIdx.y & 7;

    for (int p = tid; p < 400; p += 256) {
        int py = p / 20, px = p - py * 20;
        int gy = ty0 + py - 2, gx = tx0 + px - 2;
        bool ok = (gy >= 0 && gy < 128 && gx >= 0 && gx < 128);
        const float4* src = (const float4*)(X + ((b * 128 + gy) * 128 + gx) * 256 + g * 32);
#pragma unroll
        for (int c8 = 0; c8 < 8; c8++) {
            float4 v = ok ? src[c8] : make_float4(0.f, 0.f, 0.f, 0.f);
            float4 w = make_float4(to_tf32(v.x), to_tf32(v.y), to_tf32(v.z), to_tf32(v.w));
            *(float4*)&patch[p * 36 + c8 * 4] = w;
        }
    }

    const int wic = tid >> 3, woc = (tid & 7) * 8;
    {
        const float4* gp = (const float4*)(Wc + (0 * 32 + wic) * 512 + g * 64 + woc);
        float4 r0 = gp[0], r1 = gp[1];
        float* dw = wsm + wic * 72 + woc;
        *(float4*)dw = make_float4(to_tf32(r0.x), to_tf32(r0.y), to_tf32(r0.z), to_tf32(r0.w));
        *(float4*)(dw + 4) = make_float4(to_tf32(r1.x), to_tf32(r1.y), to_tf32(r1.z), to_tf32(r1.w));
    }
    __syncthreads();

    float acc[4][4][4] = {};

#pragma unroll 1
    for (int tap = 0; tap < 25; tap++) {
        const int ky = tap / 5, kx = tap - ky * 5;
        float4 r0, r1;
        if (tap < 24) {
            const float4* gp = (const float4*)(Wc + ((tap + 1) * 32 + wic) * 512 + g * 64 + woc);
            r0 = gp[0]; r1 = gp[1];
        }
        const float* wcur = wsm + (tap & 1) * CONV_WBUF_FL;
#pragma unroll
        for (int kc = 0; kc < 4; kc++) {
            unsigned a[4][4];
#pragma unroll
            for (int i = 0; i < 4; i++) {
                const int base = ((wm * 4 + i + ky) * 20 + kx) * 36 + kc * 8;
                const int o0 = base + (lane >> 2) * 36 + (lane & 3);
                a[i][0] = __float_as_uint(patch[o0]);
                a[i][1] = __float_as_uint(patch[o0 + 8 * 36]);
                a[i][2] = __float_as_uint(patch[o0 + 4]);
                a[i][3] = __float_as_uint(patch[o0 + 8 * 36 + 4]);
            }
#pragma unroll
            for (int j = 0; j < 4; j++) {
                const int nn = wn * 32 + j * 8 + (lane >> 2);
                unsigned bf[2];
                bf[0] = __float_as_uint(wcur[(kc * 8 + (lane & 3)) * 72 + nn]);
                bf[1] = __float_as_uint(wcur[(kc * 8 + (lane & 3) + 4) * 72 + nn]);
#pragma unroll
                for (int i = 0; i < 4; i++) mma_tf32(acc[i][j], a[i], bf);
            }
        }
        if (tap < 24) {
            float* dw = wsm + ((tap + 1) & 1) * CONV_WBUF_FL + wic * 72 + woc;
            *(float4*)dw = make_float4(to_tf32(r0.x), to_tf32(r0.y), to_tf32(r0.z), to_tf32(r0.w));
            *(float4*)(dw + 4) = make_float4(to_tf32(r1.x), to_tf32(r1.y), to_tf32(r1.z), to_tf32(r1.w));
        }
        __syncthreads();
    }

    const int win = b * 64 + (tile >> 3) * 8 + (tile & 7);
    const int head = (g & 3) * 2 + wn;
    float* dst = (g < 4) ? g_k : g_v;
    float* base = dst + ((win * 8 + head) * 256) * 32;
#pragma unroll
    for (int i = 0; i < 4; i++) {
        const int p0 = wm * 64 + i * 16 + (lane >> 2);
#pragma unroll
        for (int j = 0; j < 4; j++) {
            const int col = wn * 32 + j * 8 + (lane & 3) * 2;
            const int d = col & 31;
            float b0 = bias[g * 64 + col], b1 = bias[g * 64 + col + 1];
            *(float2*)(base + p0 * 32 + d) =
                make_float2(to_tf32(acc[i][j][0] + b0), to_tf32(acc[i][j][1] + b1));
            *(float2*)(base + (p0 + 8) * 32 + d) =
                make_float2(to_tf32(acc[i][j][2] + b0), to_tf32(acc[i][j][3] + b1));
        }
    }
}

// ---------------------------------------------------------------------------
// tf32 GEMM: MODE 0 qproj (-> g_q, tf32-rounded), MODE 1 outproj (g_o -> out)
// ---------------------------------------------------------------------------
#define GEMM_ABUF_FL 4608    // 128*36
#define GEMM_BBUF_FL 2304    // 32*72
#define GEMM_SMEM_B  ((2*GEMM_ABUF_FL + 2*GEMM_BBUF_FL) * 4)

template <int MODE>
__global__ __launch_bounds__(256, 2) void gemm_mma(const float* __restrict__ Aparam,
                                                   const float* __restrict__ Wm,
                                                   const float* __restrict__ bias,
                                                   const float* __restrict__ rz,
                                                   float* __restrict__ out) {
    extern __shared__ float smem[];
    float* as = smem;
    float* bs = smem + 2 * GEMM_ABUF_FL;

    const float* A = (MODE == 1) ? (const float*)g_o : Aparam;

    const int tid = threadIdx.x;
    const int lane = tid & 31, warp = tid >> 5;
    const int wm = warp & 3, wn = warp >> 2;
    const int m0 = blockIdx.x * 128;
    const int n0 = blockIdx.y * 64;

    const int arow = tid >> 1, akoff = (tid & 1) * 16;
    const int wic = tid >> 3, woc = (tid & 7) * 8;

    {
        const float4* ga = (const float4*)(A + (m0 + arow) * 256 + akoff);
        float* da = as + arow * 36 + akoff;
#pragma unroll
        for (int c4 = 0; c4 < 4; c4++) {
            float4 v = ga[c4];
            *(float4*)(da + c4 * 4) = make_float4(to_tf32(v.x), to_tf32(v.y), to_tf32(v.z), to_tf32(v.w));
        }
        const float4* gb = (const float4*)(Wm + wic * 256 + n0 + woc);
        float4 r0 = gb[0], r1 = gb[1];
        float* db = bs + wic * 72 + woc;
        *(float4*)db = make_float4(to_tf32(r0.x), to_tf32(r0.y), to_tf32(r0.z), to_tf32(r0.w));
        *(float4*)(db + 4) = make_float4(to_tf32(r1.x), to_tf32(r1.y), to_tf32(r1.z), to_tf32(r1.w));
    }
    __syncthreads();

    float acc[2][4][4] = {};

#pragma unroll 1
    for (int kt = 0; kt < 8; kt++) {
        float4 pa[4], pb0, pb1;
        if (kt < 7) {
            const float4* ga = (const float4*)(A + (m0 + arow) * 256 + (kt + 1) * 32 + akoff);
#pragma unroll
            for (int c4 = 0; c4 < 4; c4++) pa[c4] = ga[c4];
            const float4* gb = (const float4*)(Wm + ((kt + 1) * 32 + wic) * 256 + n0 + woc);
            pb0 = gb[0]; pb1 = gb[1];
        }
        const float* acur = as + (kt & 1) * GEMM_ABUF_FL;
        const float* bcur = bs + (kt & 1) * GEMM_BBUF_FL;
#pragma unroll
        for (int kc = 0; kc < 4; kc++) {
            unsigned a[2][4];
#pragma unroll
            for (int i = 0; i < 2; i++) {
                const int o0 = (wm * 32 + i * 16 + (lane >> 2)) * 36 + kc * 8 + (lane & 3);
                a[i][0] = __float_as_uint(acur[o0]);
                a[i][1] = __float_as_uint(acur[o0 + 8 * 36]);
                a[i][2] = __float_as_uint(acur[o0 + 4]);
                a[i][3] = __float_as_uint(acur[o0 + 8 * 36 + 4]);
            }
#pragma unroll
            for (int j = 0; j < 4; j++) {
                const int nn = wn * 32 + j * 8 + (lane >> 2);
                unsigned bf[2];
                bf[0] = __float_as_uint(bcur[(kc * 8 + (lane & 3)) * 72 + nn]);
                bf[1] = __float_as_uint(bcur[(kc * 8 + (lane & 3) + 4) * 72 + nn]);
#pragma unroll
                for (int i = 0; i < 2; i++) mma_tf32(acc[i][j], a[i], bf);
            }
        }
        if (kt < 7) {
            float* da = as + ((kt + 1) & 1) * GEMM_ABUF_FL + arow * 36 + akoff;
#pragma unroll
            for (int c4 = 0; c4 < 4; c4++)
                *(float4*)(da + c4 * 4) = make_float4(to_tf32(pa[c4].x), to_tf32(pa[c4].y),
                                                      to_tf32(pa[c4].z), to_tf32(pa[c4].w));
            float* db = bs + ((kt + 1) & 1) * GEMM_BBUF_FL + wic * 72 + woc;
            *(float4*)db = make_float4(to_tf32(pb0.x), to_tf32(pb0.y), to_tf32(pb0.z), to_tf32(pb0.w));
            *(float4*)(db + 4) = make_float4(to_tf32(pb1.x), to_tf32(pb1.y), to_tf32(pb1.z), to_tf32(pb1.w));
        }
        __syncthreads();
    }

    const float scale = 0.17677669529663687f;
    const float r = (MODE == 1) ? rz[0] : 0.f;
#pragma unroll
    for (int i = 0; i < 2; i++) {
        const int m = m0 + wm * 32 + i * 16 + (lane >> 2);
#pragma unroll
        for (int j = 0; j < 4; j++) {
            const int col = n0 + wn * 32 + j * 8 + (lane & 3) * 2;
            const float b0 = bias[col], b1 = bias[col + 1];
            if (MODE == 0) {
                const int bi = m >> 14, rr = (m >> 7) & 127, cc = m & 127;
                const int win = bi * 64 + ((rr >> 4) << 3) + (cc >> 4);
                const int t = (rr & 15) * 16 + (cc & 15);
                const int head = col >> 5, d = col & 31;
                float* p = g_q + ((win * 8 + head) * 256 + t) * 32 + d;
                *(float2*)p = make_float2(to_tf32((acc[i][j][0] + b0) * scale),
                                          to_tf32((acc[i][j][1] + b1) * scale));
                *(float2*)(p + 8 * 32) = make_float2(to_tf32((acc[i][j][2] + b0) * scale),
                                                     to_tf32((acc[i][j][3] + b1) * scale));
            } else {
                float* p = out + m * 256 + col;
                *(float2*)p = make_float2(r * (acc[i][j][0] + b0), r * (acc[i][j][1] + b1));
                *(float2*)(p + 8 * 256) = make_float2(r * (acc[i][j][2] + b0), r * (acc[i][j][3] + b1));
            }
        }
    }
}

// ---------------------------------------------------------------------------
// Tensor-core flash attention v2. Block = (window, head), 8 warps, warp owns
// 32 query rows; keys streamed in 32-key chunks (8 chunks).
// P conversion via per-warp smem round-trip (no shuffles):
//   softmax writes P tile (32x32, pitch 36) to warp-private smem; PV reads
//   A-fragments back conflict-free (bank = 4q+t). Two M-tiles processed
//   sequentially to keep live registers ~half -> 2 blocks/SM.
// ---------------------------------------------------------------------------
#define ATT_QS 9216   // 256*36
#define ATT_KS 1152   // 32*36
#define ATT_VS 1280   // 32*40
#define ATT_PS 9216   // 8 warps * 32*36
#define ATT_SMEM_B ((ATT_QS + ATT_KS + ATT_VS + ATT_PS) * 4)

__global__ __launch_bounds__(256, 2) void attn_mma() {
    extern __shared__ float sm[];
    float* Qs = sm;
    float* Ks = sm + ATT_QS;
    float* Vs = Ks + ATT_KS;
    float* Ps = Vs + ATT_VS;

    const int win = blockIdx.x, hd = blockIdx.y;
    const int tid = threadIdx.x;
    const int lane = tid & 31, warp = tid >> 5;
    const int q = lane >> 2, t = lane & 3;
    const int wb = warp * 32;
    float* Pw = Ps + warp * 1152;

    const float* qb = g_q + (win * 8 + hd) * 8192;
    const float* kb = g_k + (win * 8 + hd) * 8192;
    const float* vb = g_v + (win * 8 + hd) * 8192;
    const float* bb = g_bias + (hd << 16);

    // Stage Q (persistent) and chunk 0 of K/V
    for (int i = tid; i < 2048; i += 256) {
        float4 v = ((const float4*)qb)[i];
        *(float4*)&Qs[(i >> 3) * 36 + (i & 7) * 4] = v;
    }
    {
        float4 k0 = ((const float4*)kb)[tid];
        float4 v0 = ((const float4*)vb)[tid];
        *(float4*)&Ks[(tid >> 3) * 36 + (tid & 7) * 4] = k0;
        *(float4*)&Vs[(tid >> 3) * 40 + (tid & 7) * 4] = v0;
    }
    __syncthreads();

    float o[2][4][4] = {};
    float mrow[2][2] = {{-1e30f, -1e30f}, {-1e30f, -1e30f}};
    float lrow[2][2] = {};

#pragma unroll 1
    for (int sb = 0; sb < 8; sb++) {
        // prefetch next 32-key chunk (one float4 of K and V per thread)
        float4 kn, vn;
        if (sb < 7) {
            kn = ((const float4*)(kb + (sb + 1) * 1024))[tid];
            vn = ((const float4*)(vb + (sb + 1) * 1024))[tid];
        }

        // S = Q K^T, softmax, P -> warp-private smem; one 16-row tile at a time
#pragma unroll
        for (int mt = 0; mt < 2; mt++) {
            float s[4][4] = {};
#pragma unroll
            for (int kc = 0; kc < 4; kc++) {
                unsigned qa[4];
                const int o0 = (wb + mt * 16 + q) * 36 + kc * 8 + t;
                qa[0] = __float_as_uint(Qs[o0]);
                qa[1] = __float_as_uint(Qs[o0 + 8 * 36]);
                qa[2] = __float_as_uint(Qs[o0 + 4]);
                qa[3] = __float_as_uint(Qs[o0 + 8 * 36 + 4]);
#pragma unroll
                for (int nt = 0; nt < 4; nt++) {
                    const int ba = (nt * 8 + q) * 36 + kc * 8 + t;
                    unsigned bf[2];
                    bf[0] = __float_as_uint(Ks[ba]);
                    bf[1] = __float_as_uint(Ks[ba + 4]);
                    mma_tf32(s[nt], qa, bf);
                }
            }
            const int r0 = wb + mt * 16 + q;
#pragma unroll
            for (int nt = 0; nt < 4; nt++) {
                const int c0 = sb * 32 + nt * 8 + t * 2;
                float2 bv0 = *(const float2*)&bb[r0 * 256 + c0];
                float2 bv1 = *(const float2*)&bb[(r0 + 8) * 256 + c0];
                s[nt][0] += bv0.x; s[nt][1] += bv0.y;
                s[nt][2] += bv1.x; s[nt][3] += bv1.y;
            }
            float mx0 = -1e30f, mx1 = -1e30f;
#pragma unroll
            for (int nt = 0; nt < 4; nt++) {
                mx0 = fmaxf(mx0, fmaxf(s[nt][0], s[nt][1]));
                mx1 = fmaxf(mx1, fmaxf(s[nt][2], s[nt][3]));
            }
            mx0 = fmaxf(mx0, __shfl_xor_sync(0xffffffff, mx0, 1));
            mx0 = fmaxf(mx0, __shfl_xor_sync(0xffffffff, mx0, 2));
            mx1 = fmaxf(mx1, __shfl_xor_sync(0xffffffff, mx1, 1));
            mx1 = fmaxf(mx1, __shfl_xor_sync(0xffffffff, mx1, 2));
            const float mn0 = fmaxf(mrow[mt][0], mx0);
            const float mn1 = fmaxf(mrow[mt][1], mx1);
            const float cor0 = __expf(mrow[mt][0] - mn0);
            const float cor1 = __expf(mrow[mt][1] - mn1);
            mrow[mt][0] = mn0; mrow[mt][1] = mn1;
#pragma unroll
            for (int dn = 0; dn < 4; dn++) {
                o[mt][dn][0] *= cor0; o[mt][dn][1] *= cor0;
                o[mt][dn][2] *= cor1; o[mt][dn][3] *= cor1;
            }
            float sm0 = 0.f, sm1 = 0.f;
#pragma unroll
            for (int nt = 0; nt < 4; nt++) {
                float p0 = __expf(s[nt][0] - mn0);
                float p1 = __expf(s[nt][1] - mn0);
                float p2 = __expf(s[nt][2] - mn1);
                float p3 = __expf(s[nt][3] - mn1);
                sm0 += p0 + p1; sm1 += p2 + p3;
                *(float2*)&Pw[(mt * 16 + q) * 36 + nt * 8 + 2 * t] =
                    make_float2(to_tf32(p0), to_tf32(p1));
                *(float2*)&Pw[(mt * 16 + q + 8) * 36 + nt * 8 + 2 * t] =
                    make_float2(to_tf32(p2), to_tf32(p3));
            }
            sm0 += __shfl_xor_sync(0xffffffff, sm0, 1);
            sm0 += __shfl_xor_sync(0xffffffff, sm0, 2);
            sm1 += __shfl_xor_sync(0xffffffff, sm1, 1);
            sm1 += __shfl_xor_sync(0xffffffff, sm1, 2);
            lrow[mt][0] = lrow[mt][0] * cor0 + sm0;
            lrow[mt][1] = lrow[mt][1] * cor1 + sm1;
        }
        __syncwarp();

        // O += P V : A-fragments of P loaded from warp-private smem
#pragma unroll
        for (int kk = 0; kk < 4; kk++) {
            unsigned pa[2][4];
#pragma unroll
            for (int mt = 0; mt < 2; mt++) {
                const int pb = (mt * 16 + q) * 36 + kk * 8 + t;
                pa[mt][0] = __float_as_uint(Pw[pb]);
                pa[mt][1] = __float_as_uint(Pw[pb + 8 * 36]);
                pa[mt][2] = __float_as_uint(Pw[pb + 4]);
                pa[mt][3] = __float_as_uint(Pw[pb + 8 * 36 + 4]);
            }
#pragma unroll
            for (int dn = 0; dn < 4; dn++) {
                const int va = (kk * 8 + t) * 40 + dn * 8 + q;
                unsigned bf[2];
                bf[0] = __float_as_uint(Vs[va]);
                bf[1] = __float_as_uint(Vs[va + 4 * 40]);
                mma_tf32(o[0][dn], pa[0], bf);
                mma_tf32(o[1][dn], pa[1], bf);
            }
        }

        __syncthreads();
        if (sb < 7) {
            *(float4*)&Ks[(tid >> 3) * 36 + (tid & 7) * 4] = kn;
            *(float4*)&Vs[(tid >> 3) * 40 + (tid & 7) * 4] = vn;
        }
        __syncthreads();
    }

    // Epilogue: normalize, write to (B,H,W,C) layout in g_o
    const int bimg = win >> 6, wh = (win >> 3) & 7, ww = win & 7;
#pragma unroll
    for (int mt = 0; mt < 2; mt++) {
        const float inv0 = 1.f / lrow[mt][0];
        const float inv1 = 1.f / lrow[mt][1];
        const int tk0 = wb + mt * 16 + q;
#pragma unroll
        for (int half = 0; half < 2; half++) {
            const int tk = tk0 + half * 8;
            const float inv = half ? inv1 : inv0;
            const int gr = wh * 16 + (tk >> 4), gc = ww * 16 + (tk & 15);
            float* op = g_o + ((bimg * 128 + gr) * 128 + gc) * 256 + hd * 32;
#pragma unroll
            for (int dn = 0; dn < 4; dn++) {
                float a = o[mt][dn][half * 2] * inv;
                float b = o[mt][dn][half * 2 + 1] * inv;
                *(float2*)(op + dn * 8 + t * 2) = make_float2(a, b);
            }
        }
    }
}

// ---------------------------------------------------------------------------
extern "C" void kernel_launch(void* const* d_in, const int* in_sizes, int n_in,
                              void* d_out, int out_size) {
    (void)in_sizes; (void)n_in; (void)out_size;
    const float* x_wsa      = (const float*)d_in[0];
    const float* x_original = (const float*)d_in[1];
    const float* q_w        = (const float*)d_in[2];
    const float* q_b        = (const float*)d_in[3];
    const float* kv_w       = (const float*)d_in[4];
    const float* kv_b       = (const float*)d_in[5];
    const float* out_w      = (const float*)d_in[6];
    const float* out_b      = (const float*)d_in[7];
    const float* bias_table = (const float*)d_in[8];
    const float* rezero     = (const float*)d_in[9];
    float* out = (float*)d_out;

    cudaFuncSetAttribute(convkv_mma, cudaFuncAttributeMaxDynamicSharedMemorySize, CONV_SMEM_B);
    cudaFuncSetAttribute(gemm_mma<0>, cudaFuncAttributeMaxDynamicSharedMemorySize, GEMM_SMEM_B);
    cudaFuncSetAttribute(gemm_mma<1>, cudaFuncAttributeMaxDynamicSharedMemorySize, GEMM_SMEM_B);
    cudaFuncSetAttribute(attn_mma, cudaFuncAttributeMaxDynamicSharedMemorySize, ATT_SMEM_B);

    bias_expand<<<dim3(256, 8), 256>>>(bias_table);
    gemm_mma<0><<<dim3(512, 4), 256, GEMM_SMEM_B>>>(x_wsa, q_w, q_b, nullptr, nullptr);
    convkv_mma<<<dim3(64, 32), 256, CONV_SMEM_B>>>(x_original, kv_w, kv_b);
    attn_mma<<<dim3(256, 8), 256, ATT_SMEM_B>>>();
    gemm_mma<1><<<dim3(512, 4), 256, GEMM_SMEM_B>>>(nullptr, out_w, out_b, rezero, out);
}

// round 6
// speedup vs baseline: 3.9509x; 1.0560x over previous
#include <cuda_runtime.h>

// B=4, H=W=128, C=256, heads=8, d=32, win=16 -> 256 windows x 256 tokens
__device__ float g_q[16777216];
__device__ float g_k[16777216];
__device__ float g_v[16777216];
__device__ float g_o[16777216];
__device__ float g_bias[524288];   // [head][256 q][256 k], pre-scaled by log2(e)

__device__ __forceinline__ float to_tf32(float x) {
    unsigned u;
    asm("cvt.rna.tf32.f32 %0, %1;" : "=r"(u) : "f"(x));
    return __uint_as_float(u);
}

__device__ __forceinline__ float ex2(float x) {
    float r;
    asm("ex2.approx.ftz.f32 %0, %1;" : "=f"(r) : "f"(x));
    return r;
}

__device__ __forceinline__ void mma_tf32(float* c, const unsigned* a, const unsigned* b) {
    asm volatile(
        "mma.sync.aligned.m16n8k8.row.col.f32.tf32.tf32.f32 "
        "{%0,%1,%2,%3},{%4,%5,%6,%7},{%8,%9},{%0,%1,%2,%3};"
        : "+f"(c[0]), "+f"(c[1]), "+f"(c[2]), "+f"(c[3])
        : "r"(a[0]), "r"(a[1]), "r"(a[2]), "r"(a[3]), "r"(b[0]), "r"(b[1]));
}

// tf32 fragments via b16 ldmatrix: an 8-row x 4-float block is isomorphic to
// a b16 8x8 tile (lane l gets 4 bytes at row l/4, 4B-col l%4).
__device__ __forceinline__ void ldsm4(unsigned* r, const float* p) {
    unsigned a = (unsigned)__cvta_generic_to_shared(p);
    asm volatile("ldmatrix.sync.aligned.m8n8.x4.shared.b16 {%0,%1,%2,%3}, [%4];"
                 : "=r"(r[0]), "=r"(r[1]), "=r"(r[2]), "=r"(r[3]) : "r"(a));
}

__device__ __forceinline__ void cpa16(float* dst, const float* src) {
    unsigned d = (unsigned)__cvta_generic_to_shared(dst);
    asm volatile("cp.async.cg.shared.global [%0], [%1], 16;" :: "r"(d), "l"(src));
}

// ---------------------------------------------------------------------------
// Bias expansion: g_bias[hd][q][k] = bias_table[rel_index(q,k)][hd] * log2(e)
// ---------------------------------------------------------------------------
__global__ void bias_expand(const float* __restrict__ bt) {
    const int kt = threadIdx.x, qt = blockIdx.x, hd = blockIdx.y;
    const int qy = qt >> 4, qx = qt & 15, ky = kt >> 4, kx = kt & 15;
    const int rel = (qy - ky + 15) * 31 + (qx - kx + 15);
    g_bias[(hd << 16) + (qt << 8) + kt] = bt[rel * 8 + hd] * 1.4426950408889634f;
}

// ---------------------------------------------------------------------------
// Conv 5x5 grouped (pad 2, groups=8) as implicit GEMM on tensor cores.
// ---------------------------------------------------------------------------
#define CONV_PATCH_FL 14400   // 20*20*36
#define CONV_WBUF_FL  2304    // 32*72
#define CONV_SMEM_B   ((CONV_PATCH_FL + 2*CONV_WBUF_FL) * 4)

__global__ __launch_bounds__(256, 2) void convkv_mma(const float* __restrict__ X,
                                                     const float* __restrict__ Wc,
                                                     const float* __restrict__ bias) {
    extern __shared__ float smem[];
    float* patch = smem;
    float* wsm = smem + CONV_PATCH_FL;

    const int tid = threadIdx.x;
    const int lane = tid & 31, warp = tid >> 5;
    const int wm = warp & 3, wn = warp >> 2;
    const int g8 = lane >> 3, r8 = lane & 7;      // ldmatrix lane groups
    const int tile = blockIdx.x;
    const int ty0 = (tile >> 3) * 16, tx0 = (tile & 7) * 16;
    const int b = blockIdx.y >> 3, g = blockIdx.y & 7;

    for (int p = tid; p < 400; p += 256) {
        int py = p / 20, px = p - py * 20;
        int gy = ty0 + py - 2, gx = tx0 + px - 2;
        bool ok = (gy >= 0 && gy < 128 && gx >= 0 && gx < 128);
        const float4* src = (const float4*)(X + ((b * 128 + gy) * 128 + gx) * 256 + g * 32);
#pragma unroll
        for (int c8 = 0; c8 < 8; c8++) {
            float4 v = ok ? src[c8] : make_float4(0.f, 0.f, 0.f, 0.f);
            float4 w = make_float4(to_tf32(v.x), to_tf32(v.y), to_tf32(v.z), to_tf32(v.w));
            *(float4*)&patch[p * 36 + c8 * 4] = w;
        }
    }

    const int wic = tid >> 3, woc = (tid & 7) * 8;
    {
        const float4* gp = (const float4*)(Wc + (0 * 32 + wic) * 512 + g * 64 + woc);
        float4 r0 = gp[0], r1 = gp[1];
        float* dw = wsm + wic * 72 + woc;
        *(float4*)dw = make_float4(to_tf32(r0.x), to_tf32(r0.y), to_tf32(r0.z), to_tf32(r0.w));
        *(float4*)(dw + 4) = make_float4(to_tf32(r1.x), to_tf32(r1.y), to_tf32(r1.z), to_tf32(r1.w));
    }
    __syncthreads();

    float acc[4][4][4] = {};

#pragma unroll 1
    for (int tap = 0; tap < 25; tap++) {
        const int ky = tap / 5, kx = tap - ky * 5;
        float4 r0, r1;
        if (tap < 24) {
            const float4* gp = (const float4*)(Wc + ((tap + 1) * 32 + wic) * 512 + g * 64 + woc);
            r0 = gp[0]; r1 = gp[1];
        }
        const float* wcur = wsm + (tap & 1) * CONV_WBUF_FL;
#pragma unroll
        for (int kc = 0; kc < 4; kc++) {
            unsigned a[4][4];
#pragma unroll
            for (int i = 0; i < 4; i++) {
                // A-tile rows: sy = wm*4+i (fixed), sx = row index; ldmatrix x4
                const float* ap = patch + ((wm * 4 + i + ky) * 20 + (g8 & 1) * 8 + r8 + kx) * 36
                                  + kc * 8 + (g8 >> 1) * 4;
                ldsm4(a[i], ap);
            }
#pragma unroll
            for (int j = 0; j < 4; j++) {
                const int nn = wn * 32 + j * 8 + (lane >> 2);
                unsigned bf[2];
                bf[0] = __float_as_uint(wcur[(kc * 8 + (lane & 3)) * 72 + nn]);
                bf[1] = __float_as_uint(wcur[(kc * 8 + (lane & 3) + 4) * 72 + nn]);
#pragma unroll
                for (int i = 0; i < 4; i++) mma_tf32(acc[i][j], a[i], bf);
            }
        }
        if (tap < 24) {
            float* dw = wsm + ((tap + 1) & 1) * CONV_WBUF_FL + wic * 72 + woc;
            *(float4*)dw = make_float4(to_tf32(r0.x), to_tf32(r0.y), to_tf32(r0.z), to_tf32(r0.w));
            *(float4*)(dw + 4) = make_float4(to_tf32(r1.x), to_tf32(r1.y), to_tf32(r1.z), to_tf32(r1.w));
        }
        __syncthreads();
    }

    const int win = b * 64 + (tile >> 3) * 8 + (tile & 7);
    const int head = (g & 3) * 2 + wn;
    float* dst = (g < 4) ? g_k : g_v;
    float* base = dst + ((win * 8 + head) * 256) * 32;
#pragma unroll
    for (int i = 0; i < 4; i++) {
        const int p0 = wm * 64 + i * 16 + (lane >> 2);
#pragma unroll
        for (int j = 0; j < 4; j++) {
            const int col = wn * 32 + j * 8 + (lane & 3) * 2;
            const int d = col & 31;
            float b0 = bias[g * 64 + col], b1 = bias[g * 64 + col + 1];
            *(float2*)(base + p0 * 32 + d) =
                make_float2(to_tf32(acc[i][j][0] + b0), to_tf32(acc[i][j][1] + b1));
            *(float2*)(base + (p0 + 8) * 32 + d) =
                make_float2(to_tf32(acc[i][j][2] + b0), to_tf32(acc[i][j][3] + b1));
        }
    }
}

// ---------------------------------------------------------------------------
// tf32 GEMM: MODE 0 qproj (-> g_q with scale*log2e), MODE 1 outproj (g_o->out)
// ---------------------------------------------------------------------------
#define GEMM_ABUF_FL 4608    // 128*36
#define GEMM_BBUF_FL 2304    // 32*72
#define GEMM_SMEM_B  ((2*GEMM_ABUF_FL + 2*GEMM_BBUF_FL) * 4)

template <int MODE>
__global__ __launch_bounds__(256, 2) void gemm_mma(const float* __restrict__ Aparam,
                                                   const float* __restrict__ Wm,
                                                   const float* __restrict__ bias,
                                                   const float* __restrict__ rz,
                                                   float* __restrict__ out) {
    extern __shared__ float smem[];
    float* as = smem;
    float* bs = smem + 2 * GEMM_ABUF_FL;

    const float* A = (MODE == 1) ? (const float*)g_o : Aparam;

    const int tid = threadIdx.x;
    const int lane = tid & 31, warp = tid >> 5;
    const int wm = warp & 3, wn = warp >> 2;
    const int g8 = lane >> 3, r8 = lane & 7;
    const int m0 = blockIdx.x * 128;
    const int n0 = blockIdx.y * 64;

    const int arow = tid >> 1, akoff = (tid & 1) * 16;
    const int wic = tid >> 3, woc = (tid & 7) * 8;

    {
        const float4* ga = (const float4*)(A + (m0 + arow) * 256 + akoff);
        float* da = as + arow * 36 + akoff;
#pragma unroll
        for (int c4 = 0; c4 < 4; c4++) {
            float4 v = ga[c4];
            *(float4*)(da + c4 * 4) = make_float4(to_tf32(v.x), to_tf32(v.y), to_tf32(v.z), to_tf32(v.w));
        }
        const float4* gb = (const float4*)(Wm + wic * 256 + n0 + woc);
        float4 r0 = gb[0], r1 = gb[1];
        float* db = bs + wic * 72 + woc;
        *(float4*)db = make_float4(to_tf32(r0.x), to_tf32(r0.y), to_tf32(r0.z), to_tf32(r0.w));
        *(float4*)(db + 4) = make_float4(to_tf32(r1.x), to_tf32(r1.y), to_tf32(r1.z), to_tf32(r1.w));
    }
    __syncthreads();

    float acc[2][4][4] = {};

#pragma unroll 1
    for (int kt = 0; kt < 8; kt++) {
        float4 pa[4], pb0, pb1;
        if (kt < 7) {
            const float4* ga = (const float4*)(A + (m0 + arow) * 256 + (kt + 1) * 32 + akoff);
#pragma unroll
            for (int c4 = 0; c4 < 4; c4++) pa[c4] = ga[c4];
            const float4* gb = (const float4*)(Wm + ((kt + 1) * 32 + wic) * 256 + n0 + woc);
            pb0 = gb[0]; pb1 = gb[1];
        }
        const float* acur = as + (kt & 1) * GEMM_ABUF_FL;
        const float* bcur = bs + (kt & 1) * GEMM_BBUF_FL;
#pragma unroll
        for (int kc = 0; kc < 4; kc++) {
            unsigned a[2][4];
#pragma unroll
            for (int i = 0; i < 2; i++) {
                const float* ap = acur + (wm * 32 + i * 16 + (g8 & 1) * 8 + r8) * 36
                                  + kc * 8 + (g8 >> 1) * 4;
                ldsm4(a[i], ap);
            }
#pragma unroll
            for (int j = 0; j < 4; j++) {
                const int nn = wn * 32 + j * 8 + (lane >> 2);
                unsigned bf[2];
                bf[0] = __float_as_uint(bcur[(kc * 8 + (lane & 3)) * 72 + nn]);
                bf[1] = __float_as_uint(bcur[(kc * 8 + (lane & 3) + 4) * 72 + nn]);
#pragma unroll
                for (int i = 0; i < 2; i++) mma_tf32(acc[i][j], a[i], bf);
            }
        }
        if (kt < 7) {
            float* da = as + ((kt + 1) & 1) * GEMM_ABUF_FL + arow * 36 + akoff;
#pragma unroll
            for (int c4 = 0; c4 < 4; c4++)
                *(float4*)(da + c4 * 4) = make_float4(to_tf32(pa[c4].x), to_tf32(pa[c4].y),
                                                      to_tf32(pa[c4].z), to_tf32(pa[c4].w));
            float* db = bs + ((kt + 1) & 1) * GEMM_BBUF_FL + wic * 72 + woc;
            *(float4*)db = make_float4(to_tf32(pb0.x), to_tf32(pb0.y), to_tf32(pb0.z), to_tf32(pb0.w));
            *(float4*)(db + 4) = make_float4(to_tf32(pb1.x), to_tf32(pb1.y), to_tf32(pb1.z), to_tf32(pb1.w));
        }
        __syncthreads();
    }

    // qproj folds log2(e) so attention can use raw ex2
    const float scale = 0.17677669529663687f * 1.4426950408889634f;
    const float r = (MODE == 1) ? rz[0] : 0.f;
#pragma unroll
    for (int i = 0; i < 2; i++) {
        const int m = m0 + wm * 32 + i * 16 + (lane >> 2);
#pragma unroll
        for (int j = 0; j < 4; j++) {
            const int col = n0 + wn * 32 + j * 8 + (lane & 3) * 2;
            const float b0 = bias[col], b1 = bias[col + 1];
            if (MODE == 0) {
                const int bi = m >> 14, rr = (m >> 7) & 127, cc = m & 127;
                const int win = bi * 64 + ((rr >> 4) << 3) + (cc >> 4);
                const int t = (rr & 15) * 16 + (cc & 15);
                const int head = col >> 5, d = col & 31;
                float* p = g_q + ((win * 8 + head) * 256 + t) * 32 + d;
                *(float2*)p = make_float2(to_tf32((acc[i][j][0] + b0) * scale),
                                          to_tf32((acc[i][j][1] + b1) * scale));
                *(float2*)(p + 8 * 32) = make_float2(to_tf32((acc[i][j][2] + b0) * scale),
                                                     to_tf32((acc[i][j][3] + b1) * scale));
            } else {
                float* p = out + m * 256 + col;
                *(float2*)p = make_float2(r * (acc[i][j][0] + b0), r * (acc[i][j][1] + b1));
                *(float2*)(p + 8 * 256) = make_float2(r * (acc[i][j][2] + b0), r * (acc[i][j][3] + b1));
            }
        }
    }
}

// ---------------------------------------------------------------------------
// Tensor-core flash attention v3.
//  - Q fragments register-resident (loaded once via ldmatrix)
//  - K fragments via ldmatrix.x4; V via conflict-free LDS.32
//  - K/V streamed with cp.async, 3-stage ring, ONE __syncthreads per chunk
//  - bias preloaded as mma accumulator init; softmax in log2 domain (ex2)
//  - P round-trips through warp-private smem, reloaded via ldmatrix
// ---------------------------------------------------------------------------
#define ATT_QS 9216            // 256*36
#define ATT_KS (3*1152)        // 3 stages * 32*36
#define ATT_VS (3*1152)
#define ATT_PS 9216            // 8 warps * 32*36
#define ATT_SMEM_B ((ATT_QS + ATT_KS + ATT_VS + ATT_PS) * 4)

__global__ __launch_bounds__(256, 2) void attn_mma() {
    extern __shared__ float sm[];
    float* Qs = sm;
    float* Ks = sm + ATT_QS;
    float* Vs = Ks + ATT_KS;
    float* Ps = Vs + ATT_VS;

    const int win = blockIdx.x, hd = blockIdx.y;
    const int tid = threadIdx.x;
    const int lane = tid & 31, warp = tid >> 5;
    const int q = lane >> 2, t = lane & 3;
    const int g8 = lane >> 3, r8 = lane & 7;
    const int wb = warp * 32;
    float* Pw = Ps + warp * 1152;

    const float* qb = g_q + (win * 8 + hd) * 8192;
    const float* kb = g_k + (win * 8 + hd) * 8192;
    const float* vb = g_v + (win * 8 + hd) * 8192;
    const float* bb = g_bias + (hd << 16);

    // Stage Q into smem (pitch 36)
    for (int i = tid; i < 2048; i += 256) {
        float4 v = ((const float4*)qb)[i];
        *(float4*)&Qs[(i >> 3) * 36 + (i & 7) * 4] = v;
    }
    // cp.async chunks 0 and 1 of K/V (each chunk: 32 keys x 32 d)
    {
        const int key = tid >> 3, d4 = (tid & 7) * 4;
#pragma unroll
        for (int c = 0; c < 2; c++) {
            cpa16(Ks + c * 1152 + key * 36 + d4, kb + c * 1024 + tid * 4);
            cpa16(Vs + c * 1152 + key * 36 + d4, vb + c * 1024 + tid * 4);
            asm volatile("cp.async.commit_group;");
        }
    }
    __syncthreads();   // Qs visible

    // Q fragments -> registers (once)
    unsigned qa[2][4][4];
#pragma unroll
    for (int mt = 0; mt < 2; mt++)
#pragma unroll
        for (int kc = 0; kc < 4; kc++)
            ldsm4(qa[mt][kc], Qs + (wb + mt * 16 + (g8 & 1) * 8 + r8) * 36 + kc * 8 + (g8 >> 1) * 4);

    float o[2][4][4] = {};
    float mrow[2][2] = {{-1e30f, -1e30f}, {-1e30f, -1e30f}};
    float lrow[2][2] = {};

#pragma unroll 1
    for (int sb = 0; sb < 8; sb++) {
        asm volatile("cp.async.wait_group 1;");
        __syncthreads();   // chunk sb visible in all threads

        // issue chunk sb+2 into ring slot (sb+2)%3 (nobody reads it now)
        if (sb < 6) {
            const int slot = (sb + 2) % 3;
            const int key = tid >> 3, d4 = (tid & 7) * 4;
            cpa16(Ks + slot * 1152 + key * 36 + d4, kb + (sb + 2) * 1024 + tid * 4);
            cpa16(Vs + slot * 1152 + key * 36 + d4, vb + (sb + 2) * 1024 + tid * 4);
        }
        asm volatile("cp.async.commit_group;");   // (empty group when sb>=6)

        const float* Kb = Ks + (sb % 3) * 1152;
        const float* Vb = Vs + (sb % 3) * 1152;

        // ---- S = Q K^T (+bias as accumulator init), softmax, P -> smem ----
#pragma unroll
        for (int mt = 0; mt < 2; mt++) {
            float s[4][4];
            const int r0 = wb + mt * 16 + q;
            const float* br0 = bb + r0 * 256 + sb * 32 + t * 2;
            const float* br1 = br0 + 8 * 256;
#pragma unroll
            for (int nt = 0; nt < 4; nt++) {
                float2 b0 = *(const float2*)(br0 + nt * 8);
                float2 b1 = *(const float2*)(br1 + nt * 8);
                s[nt][0] = b0.x; s[nt][1] = b0.y; s[nt][2] = b1.x; s[nt][3] = b1.y;
            }
#pragma unroll
            for (int kc = 0; kc < 4; kc++) {
#pragma unroll
                for (int pr = 0; pr < 2; pr++) {
                    unsigned kf[4];
                    ldsm4(kf, Kb + (pr * 16 + (g8 >> 1) * 8 + r8) * 36 + kc * 8 + (g8 & 1) * 4);
                    mma_tf32(s[pr * 2 + 0], qa[mt][kc], &kf[0]);
                    mma_tf32(s[pr * 2 + 1], qa[mt][kc], &kf[2]);
                }
            }
            float mx0 = fmaxf(fmaxf(s[0][0], s[0][1]), fmaxf(s[1][0], s[1][1]));
            float mx1 = fmaxf(fmaxf(s[0][2], s[0][3]), fmaxf(s[1][2], s[1][3]));
            mx0 = fmaxf(mx0, fmaxf(fmaxf(s[2][0], s[2][1]), fmaxf(s[3][0], s[3][1])));
            mx1 = fmaxf(mx1, fmaxf(fmaxf(s[2][2], s[2][3]), fmaxf(s[3][2], s[3][3])));
            mx0 = fmaxf(mx0, __shfl_xor_sync(0xffffffff, mx0, 1));
            mx0 = fmaxf(mx0, __shfl_xor_sync(0xffffffff, mx0, 2));
            mx1 = fmaxf(mx1, __shfl_xor_sync(0xffffffff, mx1, 1));
            mx1 = fmaxf(mx1, __shfl_xor_sync(0xffffffff, mx1, 2));
            const float mn0 = fmaxf(mrow[mt][0], mx0);
            const float mn1 = fmaxf(mrow[mt][1], mx1);
            const float cor0 = ex2(mrow[mt][0] - mn0);
            const float cor1 = ex2(mrow[mt][1] - mn1);
            mrow[mt][0] = mn0; mrow[mt][1] = mn1;
#pragma unroll
            for (int dn = 0; dn < 4; dn++) {
                o[mt][dn][0] *= cor0; o[mt][dn][1] *= cor0;
                o[mt][dn][2] *= cor1; o[mt][dn][3] *= cor1;
            }
            float sm0 = 0.f, sm1 = 0.f;
#pragma unroll
            for (int nt = 0; nt < 4; nt++) {
                float p0 = ex2(s[nt][0] - mn0);
                float p1 = ex2(s[nt][1] - mn0);
                float p2 = ex2(s[nt][2] - mn1);
                float p3 = ex2(s[nt][3] - mn1);
                sm0 += p0 + p1; sm1 += p2 + p3;
                *(float2*)&Pw[(mt * 16 + q) * 36 + nt * 8 + 2 * t] =
                    make_float2(to_tf32(p0), to_tf32(p1));
                *(float2*)&Pw[(mt * 16 + q + 8) * 36 + nt * 8 + 2 * t] =
                    make_float2(to_tf32(p2), to_tf32(p3));
            }
            sm0 += __shfl_xor_sync(0xffffffff, sm0, 1);
            sm0 += __shfl_xor_sync(0xffffffff, sm0, 2);
            sm1 += __shfl_xor_sync(0xffffffff, sm1, 1);
            sm1 += __shfl_xor_sync(0xffffffff, sm1, 2);
            lrow[mt][0] = lrow[mt][0] * cor0 + sm0;
            lrow[mt][1] = lrow[mt][1] * cor1 + sm1;
        }
        __syncwarp();

        // ---- O += P V ----
#pragma unroll
        for (int kk = 0; kk < 4; kk++) {
            unsigned pa[2][4];
            ldsm4(pa[0], Pw + ((g8 & 1) * 8 + r8) * 36 + kk * 8 + (g8 >> 1) * 4);
            ldsm4(pa[1], Pw + (16 + (g8 & 1) * 8 + r8) * 36 + kk * 8 + (g8 >> 1) * 4);
#pragma unroll
            for (int dn = 0; dn < 4; dn++) {
                const int va = (kk * 8 + t) * 36 + dn * 8 + q;
                unsigned bf[2];
                bf[0] = __float_as_uint(Vb[va]);
                bf[1] = __float_as_uint(Vb[va + 4 * 36]);
                mma_tf32(o[0][dn], pa[0], bf);
                mma_tf32(o[1][dn], pa[1], bf);
            }
        }
    }

    // Epilogue: normalize, write to (B,H,W,C) layout in g_o
    const int bimg = win >> 6, wh = (win >> 3) & 7, ww = win & 7;
#pragma unroll
    for (int mt = 0; mt < 2; mt++) {
        const float inv0 = 1.f / lrow[mt][0];
        const float inv1 = 1.f / lrow[mt][1];
        const int tk0 = wb + mt * 16 + q;
#pragma unroll
        for (int half = 0; half < 2; half++) {
            const int tk = tk0 + half * 8;
            const float inv = half ? inv1 : inv0;
            const int gr = wh * 16 + (tk >> 4), gc = ww * 16 + (tk & 15);
            float* op = g_o + ((bimg * 128 + gr) * 128 + gc) * 256 + hd * 32;
#pragma unroll
            for (int dn = 0; dn < 4; dn++) {
                float a = o[mt][dn][half * 2] * inv;
                float b = o[mt][dn][half * 2 + 1] * inv;
                *(float2*)(op + dn * 8 + t * 2) = make_float2(a, b);
            }
        }
    }
}

// ---------------------------------------------------------------------------
extern "C" void kernel_launch(void* const* d_in, const int* in_sizes, int n_in,
                              void* d_out, int out_size) {
    (void)in_sizes; (void)n_in; (void)out_size;
    const float* x_wsa      = (const float*)d_in[0];
    const float* x_original = (const float*)d_in[1];
    const float* q_w        = (const float*)d_in[2];
    const float* q_b        = (const float*)d_in[3];
    const float* kv_w       = (const float*)d_in[4];
    const float* kv_b       = (const float*)d_in[5];
    const float* out_w      = (const float*)d_in[6];
    const float* out_b      = (const float*)d_in[7];
    const float* bias_table = (const float*)d_in[8];
    const float* rezero     = (const float*)d_in[9];
    float* out = (float*)d_out;

    cudaFuncSetAttribute(convkv_mma, cudaFuncAttributeMaxDynamicSharedMemorySize, CONV_SMEM_B);
    cudaFuncSetAttribute(gemm_mma<0>, cudaFuncAttributeMaxDynamicSharedMemorySize, GEMM_SMEM_B);
    cudaFuncSetAttribute(gemm_mma<1>, cudaFuncAttributeMaxDynamicSharedMemorySize, GEMM_SMEM_B);
    cudaFuncSetAttribute(attn_mma, cudaFuncAttributeMaxDynamicSharedMemorySize, ATT_SMEM_B);

    bias_expand<<<dim3(256, 8), 256>>>(bias_table);
    gemm_mma<0><<<dim3(512, 4), 256, GEMM_SMEM_B>>>(x_wsa, q_w, q_b, nullptr, nullptr);
    convkv_mma<<<dim3(64, 32), 256, CONV_SMEM_B>>>(x_original, kv_w, kv_b);
    attn_mma<<<dim3(256, 8), 256, ATT_SMEM_B>>>();
    gemm_mma<1><<<dim3(512, 4), 256, GEMM_SMEM_B>>>(nullptr, out_w, out_b, rezero, out);
}

// round 7
// speedup vs baseline: 4.0163x; 1.0165x over previous
#include <cuda_runtime.h>

// B=4, H=W=128, C=256, heads=8, d=32, win=16 -> 256 windows x 256 tokens
// g_q: [win][head][tok][d]; g_k: [win][head][key][d]; g_v TRANSPOSED: [win][head][d][key]
__device__ float g_q[16777216];
__device__ float g_k[16777216];
__device__ float g_v[16777216];
__device__ float g_o[16777216];
__device__ float g_bias[524288];   // [head][256 q][256 k], pre-scaled by log2(e)

__device__ __forceinline__ float to_tf32(float x) {
    unsigned u;
    asm("cvt.rna.tf32.f32 %0, %1;" : "=r"(u) : "f"(x));
    return __uint_as_float(u);
}

__device__ __forceinline__ float ex2(float x) {
    float r;
    asm("ex2.approx.ftz.f32 %0, %1;" : "=f"(r) : "f"(x));
    return r;
}

__device__ __forceinline__ void mma_tf32(float* c, const unsigned* a, const unsigned* b) {
    asm volatile(
        "mma.sync.aligned.m16n8k8.row.col.f32.tf32.tf32.f32 "
        "{%0,%1,%2,%3},{%4,%5,%6,%7},{%8,%9},{%0,%1,%2,%3};"
        : "+f"(c[0]), "+f"(c[1]), "+f"(c[2]), "+f"(c[3])
        : "r"(a[0]), "r"(a[1]), "r"(a[2]), "r"(a[3]), "r"(b[0]), "r"(b[1]));
}

// tf32 fragments via b16 ldmatrix: an 8-row x 4-float block is isomorphic to
// a b16 8x8 tile (lane l gets 4 bytes at row l/4, 4B-col l%4).
__device__ __forceinline__ void ldsm4(unsigned* r, const float* p) {
    unsigned a = (unsigned)__cvta_generic_to_shared(p);
    asm volatile("ldmatrix.sync.aligned.m8n8.x4.shared.b16 {%0,%1,%2,%3}, [%4];"
                 : "=r"(r[0]), "=r"(r[1]), "=r"(r[2]), "=r"(r[3]) : "r"(a));
}

__device__ __forceinline__ void cpa16(float* dst, const float* src) {
    unsigned d = (unsigned)__cvta_generic_to_shared(dst);
    asm volatile("cp.async.cg.shared.global [%0], [%1], 16;" :: "r"(d), "l"(src));
}

// ---------------------------------------------------------------------------
// Bias expansion: g_bias[hd][q][k] = bias_table[rel_index(q,k)][hd] * log2(e)
// ---------------------------------------------------------------------------
__global__ void bias_expand(const float* __restrict__ bt) {
    const int kt = threadIdx.x, qt = blockIdx.x, hd = blockIdx.y;
    const int qy = qt >> 4, qx = qt & 15, ky = kt >> 4, kx = kt & 15;
    const int rel = (qy - ky + 15) * 31 + (qx - kx + 15);
    g_bias[(hd << 16) + (qt << 8) + kt] = bt[rel * 8 + hd] * 1.4426950408889634f;
}

// ---------------------------------------------------------------------------
// Conv 5x5 grouped (pad 2, groups=8) as implicit GEMM on tensor cores.
// K scattered as [key][d]; V scattered TRANSPOSED as [d][key].
// ---------------------------------------------------------------------------
#define CONV_PATCH_FL 14400   // 20*20*36
#define CONV_WBUF_FL  2304    // 32*72
#define CONV_SMEM_B   ((CONV_PATCH_FL + 2*CONV_WBUF_FL) * 4)

__global__ __launch_bounds__(256, 2) void convkv_mma(const float* __restrict__ X,
                                                     const float* __restrict__ Wc,
                                                     const float* __restrict__ bias) {
    extern __shared__ float smem[];
    float* patch = smem;
    float* wsm = smem + CONV_PATCH_FL;

    const int tid = threadIdx.x;
    const int lane = tid & 31, warp = tid >> 5;
    const int wm = warp & 3, wn = warp >> 2;
    const int g8 = lane >> 3, r8 = lane & 7;
    const int tile = blockIdx.x;
    const int ty0 = (tile >> 3) * 16, tx0 = (tile & 7) * 16;
    const int b = blockIdx.y >> 3, g = blockIdx.y & 7;

    for (int p = tid; p < 400; p += 256) {
        int py = p / 20, px = p - py * 20;
        int gy = ty0 + py - 2, gx = tx0 + px - 2;
        bool ok = (gy >= 0 && gy < 128 && gx >= 0 && gx < 128);
        const float4* src = (const float4*)(X + ((b * 128 + gy) * 128 + gx) * 256 + g * 32);
#pragma unroll
        for (int c8 = 0; c8 < 8; c8++) {
            float4 v = ok ? src[c8] : make_float4(0.f, 0.f, 0.f, 0.f);
            float4 w = make_float4(to_tf32(v.x), to_tf32(v.y), to_tf32(v.z), to_tf32(v.w));
            *(float4*)&patch[p * 36 + c8 * 4] = w;
        }
    }

    const int wic = tid >> 3, woc = (tid & 7) * 8;
    {
        const float4* gp = (const float4*)(Wc + (0 * 32 + wic) * 512 + g * 64 + woc);
        float4 r0 = gp[0], r1 = gp[1];
        float* dw = wsm + wic * 72 + woc;
        *(float4*)dw = make_float4(to_tf32(r0.x), to_tf32(r0.y), to_tf32(r0.z), to_tf32(r0.w));
        *(float4*)(dw + 4) = make_float4(to_tf32(r1.x), to_tf32(r1.y), to_tf32(r1.z), to_tf32(r1.w));
    }
    __syncthreads();

    float acc[4][4][4] = {};

#pragma unroll 1
    for (int tap = 0; tap < 25; tap++) {
        const int ky = tap / 5, kx = tap - ky * 5;
        float4 r0, r1;
        if (tap < 24) {
            const float4* gp = (const float4*)(Wc + ((tap + 1) * 32 + wic) * 512 + g * 64 + woc);
            r0 = gp[0]; r1 = gp[1];
        }
        const float* wcur = wsm + (tap & 1) * CONV_WBUF_FL;
#pragma unroll
        for (int kc = 0; kc < 4; kc++) {
            unsigned a[4][4];
#pragma unroll
            for (int i = 0; i < 4; i++) {
                const float* ap = patch + ((wm * 4 + i + ky) * 20 + (g8 & 1) * 8 + r8 + kx) * 36
                                  + kc * 8 + (g8 >> 1) * 4;
                ldsm4(a[i], ap);
            }
#pragma unroll
            for (int j = 0; j < 4; j++) {
                const int nn = wn * 32 + j * 8 + (lane >> 2);
                unsigned bf[2];
                bf[0] = __float_as_uint(wcur[(kc * 8 + (lane & 3)) * 72 + nn]);
                bf[1] = __float_as_uint(wcur[(kc * 8 + (lane & 3) + 4) * 72 + nn]);
#pragma unroll
                for (int i = 0; i < 4; i++) mma_tf32(acc[i][j], a[i], bf);
            }
        }
        if (tap < 24) {
            float* dw = wsm + ((tap + 1) & 1) * CONV_WBUF_FL + wic * 72 + woc;
            *(float4*)dw = make_float4(to_tf32(r0.x), to_tf32(r0.y), to_tf32(r0.z), to_tf32(r0.w));
            *(float4*)(dw + 4) = make_float4(to_tf32(r1.x), to_tf32(r1.y), to_tf32(r1.z), to_tf32(r1.w));
        }
        __syncthreads();
    }

    const int win = b * 64 + (tile >> 3) * 8 + (tile & 7);
    const int head = (g & 3) * 2 + wn;
    if (g < 4) {   // K: [key][d]
        float* base = g_k + ((win * 8 + head) * 256) * 32;
#pragma unroll
        for (int i = 0; i < 4; i++) {
            const int p0 = wm * 64 + i * 16 + (lane >> 2);
#pragma unroll
            for (int j = 0; j < 4; j++) {
                const int col = wn * 32 + j * 8 + (lane & 3) * 2;
                const int d = col & 31;
                float b0 = bias[g * 64 + col], b1 = bias[g * 64 + col + 1];
                *(float2*)(base + p0 * 32 + d) =
                    make_float2(to_tf32(acc[i][j][0] + b0), to_tf32(acc[i][j][1] + b1));
                *(float2*)(base + (p0 + 8) * 32 + d) =
                    make_float2(to_tf32(acc[i][j][2] + b0), to_tf32(acc[i][j][3] + b1));
            }
        }
    } else {       // V transposed: [d][key]
        float* base = g_v + ((win * 8 + head) * 32) * 256;
#pragma unroll
        for (int i = 0; i < 4; i++) {
            const int p0 = wm * 64 + i * 16 + (lane >> 2);
#pragma unroll
            for (int j = 0; j < 4; j++) {
                const int col = wn * 32 + j * 8 + (lane & 3) * 2;
                const int d0 = col & 31;
                float b0 = bias[g * 64 + col], b1 = bias[g * 64 + col + 1];
                base[d0 * 256 + p0]           = to_tf32(acc[i][j][0] + b0);
                base[(d0 + 1) * 256 + p0]     = to_tf32(acc[i][j][1] + b1);
                base[d0 * 256 + p0 + 8]       = to_tf32(acc[i][j][2] + b0);
                base[(d0 + 1) * 256 + p0 + 8] = to_tf32(acc[i][j][3] + b1);
            }
        }
    }
}

// ---------------------------------------------------------------------------
// tf32 GEMM: MODE 0 qproj (-> g_q with scale*log2e), MODE 1 outproj (g_o->out)
// ---------------------------------------------------------------------------
#define GEMM_ABUF_FL 4608    // 128*36
#define GEMM_BBUF_FL 2304    // 32*72
#define GEMM_SMEM_B  ((2*GEMM_ABUF_FL + 2*GEMM_BBUF_FL) * 4)

template <int MODE>
__global__ __launch_bounds__(256, 2) void gemm_mma(const float* __restrict__ Aparam,
                                                   const float* __restrict__ Wm,
                                                   const float* __restrict__ bias,
                                                   const float* __restrict__ rz,
                                                   float* __restrict__ out) {
    extern __shared__ float smem[];
    float* as = smem;
    float* bs = smem + 2 * GEMM_ABUF_FL;

    const float* A = (MODE == 1) ? (const float*)g_o : Aparam;

    const int tid = threadIdx.x;
    const int lane = tid & 31, warp = tid >> 5;
    const int wm = warp & 3, wn = warp >> 2;
    const int g8 = lane >> 3, r8 = lane & 7;
    const int m0 = blockIdx.x * 128;
    const int n0 = blockIdx.y * 64;

    const int arow = tid >> 1, akoff = (tid & 1) * 16;
    const int wic = tid >> 3, woc = (tid & 7) * 8;

    {
        const float4* ga = (const float4*)(A + (m0 + arow) * 256 + akoff);
        float* da = as + arow * 36 + akoff;
#pragma unroll
        for (int c4 = 0; c4 < 4; c4++) {
            float4 v = ga[c4];
            *(float4*)(da + c4 * 4) = make_float4(to_tf32(v.x), to_tf32(v.y), to_tf32(v.z), to_tf32(v.w));
        }
        const float4* gb = (const float4*)(Wm + wic * 256 + n0 + woc);
        float4 r0 = gb[0], r1 = gb[1];
        float* db = bs + wic * 72 + woc;
        *(float4*)db = make_float4(to_tf32(r0.x), to_tf32(r0.y), to_tf32(r0.z), to_tf32(r0.w));
        *(float4*)(db + 4) = make_float4(to_tf32(r1.x), to_tf32(r1.y), to_tf32(r1.z), to_tf32(r1.w));
    }
    __syncthreads();

    float acc[2][4][4] = {};

#pragma unroll 1
    for (int kt = 0; kt < 8; kt++) {
        float4 pa[4], pb0, pb1;
        if (kt < 7) {
            const float4* ga = (const float4*)(A + (m0 + arow) * 256 + (kt + 1) * 32 + akoff);
#pragma unroll
            for (int c4 = 0; c4 < 4; c4++) pa[c4] = ga[c4];
            const float4* gb = (const float4*)(Wm + ((kt + 1) * 32 + wic) * 256 + n0 + woc);
            pb0 = gb[0]; pb1 = gb[1];
        }
        const float* acur = as + (kt & 1) * GEMM_ABUF_FL;
        const float* bcur = bs + (kt & 1) * GEMM_BBUF_FL;
#pragma unroll
        for (int kc = 0; kc < 4; kc++) {
            unsigned a[2][4];
#pragma unroll
            for (int i = 0; i < 2; i++) {
                const float* ap = acur + (wm * 32 + i * 16 + (g8 & 1) * 8 + r8) * 36
                                  + kc * 8 + (g8 >> 1) * 4;
                ldsm4(a[i], ap);
            }
#pragma unroll
            for (int j = 0; j < 4; j++) {
                const int nn = wn * 32 + j * 8 + (lane >> 2);
                unsigned bf[2];
                bf[0] = __float_as_uint(bcur[(kc * 8 + (lane & 3)) * 72 + nn]);
                bf[1] = __float_as_uint(bcur[(kc * 8 + (lane & 3) + 4) * 72 + nn]);
#pragma unroll
                for (int i = 0; i < 2; i++) mma_tf32(acc[i][j], a[i], bf);
            }
        }
        if (kt < 7) {
            float* da = as + ((kt + 1) & 1) * GEMM_ABUF_FL + arow * 36 + akoff;
#pragma unroll
            for (int c4 = 0; c4 < 4; c4++)
                *(float4*)(da + c4 * 4) = make_float4(to_tf32(pa[c4].x), to_tf32(pa[c4].y),
                                                      to_tf32(pa[c4].z), to_tf32(pa[c4].w));
            float* db = bs + ((kt + 1) & 1) * GEMM_BBUF_FL + wic * 72 + woc;
            *(float4*)db = make_float4(to_tf32(pb0.x), to_tf32(pb0.y), to_tf32(pb0.z), to_tf32(pb0.w));
            *(float4*)(db + 4) = make_float4(to_tf32(pb1.x), to_tf32(pb1.y), to_tf32(pb1.z), to_tf32(pb1.w));
        }
        __syncthreads();
    }

    const float scale = 0.17677669529663687f * 1.4426950408889634f;  // qproj folds log2(e)
    const float r = (MODE == 1) ? rz[0] : 0.f;
#pragma unroll
    for (int i = 0; i < 2; i++) {
        const int m = m0 + wm * 32 + i * 16 + (lane >> 2);
#pragma unroll
        for (int j = 0; j < 4; j++) {
            const int col = n0 + wn * 32 + j * 8 + (lane & 3) * 2;
            const float b0 = bias[col], b1 = bias[col + 1];
            if (MODE == 0) {
                const int bi = m >> 14, rr = (m >> 7) & 127, cc = m & 127;
                const int win = bi * 64 + ((rr >> 4) << 3) + (cc >> 4);
                const int t = (rr & 15) * 16 + (cc & 15);
                const int head = col >> 5, d = col & 31;
                float* p = g_q + ((win * 8 + head) * 256 + t) * 32 + d;
                *(float2*)p = make_float2(to_tf32((acc[i][j][0] + b0) * scale),
                                          to_tf32((acc[i][j][1] + b1) * scale));
                *(float2*)(p + 8 * 32) = make_float2(to_tf32((acc[i][j][2] + b0) * scale),
                                                     to_tf32((acc[i][j][3] + b1) * scale));
            } else {
                float* p = out + m * 256 + col;
                *(float2*)p = make_float2(r * (acc[i][j][0] + b0), r * (acc[i][j][1] + b1));
                *(float2*)(p + 8 * 256) = make_float2(r * (acc[i][j][2] + b0), r * (acc[i][j][3] + b1));
            }
        }
    }
}

// ---------------------------------------------------------------------------
// Tensor-core flash attention v4.
//  - Q fragments register-resident; K fragments via ldmatrix, loaded ONCE per
//    chunk (S for both m-tiles computed in one pass)
//  - V stored transposed [d][key] -> B-fragments via ldmatrix (8/chunk)
//  - l-sum kept as per-lane partials, reduced once in the epilogue
//  - raw P stored (mma truncates to tf32 anyway)
//  - cp.async 3-stage ring, one __syncthreads per chunk, log2-domain softmax
// ---------------------------------------------------------------------------
#define ATT_QS 9216            // 256*36
#define ATT_KS (3*1152)        // 3 stages * 32*36
#define ATT_VS (3*1152)        // 3 stages * 32 d * 36 (keys pitch)
#define ATT_PS 9216            // 8 warps * 32*36
#define ATT_SMEM_B ((ATT_QS + ATT_KS + ATT_VS + ATT_PS) * 4)

__global__ __launch_bounds__(256, 2) void attn_mma() {
    extern __shared__ float sm[];
    float* Qs = sm;
    float* Ks = sm + ATT_QS;
    float* Vs = Ks + ATT_KS;
    float* Ps = Vs + ATT_VS;

    const int win = blockIdx.x, hd = blockIdx.y;
    const int tid = threadIdx.x;
    const int lane = tid & 31, warp = tid >> 5;
    const int q = lane >> 2, t = lane & 3;
    const int g8 = lane >> 3, r8 = lane & 7;
    const int wb = warp * 32;
    float* Pw = Ps + warp * 1152;

    const float* qb = g_q + (win * 8 + hd) * 8192;
    const float* kb = g_k + (win * 8 + hd) * 8192;
    const float* vtb = g_v + (win * 8 + hd) * 8192;   // [32 d][256 key]
    const float* bb = g_bias + (hd << 16);

    // Stage Q into smem (pitch 36)
    for (int i = tid; i < 2048; i += 256) {
        float4 v = ((const float4*)qb)[i];
        *(float4*)&Qs[(i >> 3) * 36 + (i & 7) * 4] = v;
    }
    // cp.async chunks 0 and 1. K: [key][d]; V: [d][key] slices
    {
        const int row = tid >> 3, seg = (tid & 7) * 4;
#pragma unroll
        for (int c = 0; c < 2; c++) {
            cpa16(Ks + c * 1152 + row * 36 + seg, kb + c * 1024 + tid * 4);
            cpa16(Vs + c * 1152 + row * 36 + seg, vtb + row * 256 + c * 32 + seg);
            asm volatile("cp.async.commit_group;");
        }
    }
    __syncthreads();

    // Q fragments -> registers (once)
    unsigned qa[2][4][4];
#pragma unroll
    for (int mt = 0; mt < 2; mt++)
#pragma unroll
        for (int kc = 0; kc < 4; kc++)
            ldsm4(qa[mt][kc], Qs + (wb + mt * 16 + (g8 & 1) * 8 + r8) * 36 + kc * 8 + (g8 >> 1) * 4);

    float o[2][4][4] = {};
    float mrow[2][2] = {{-1e30f, -1e30f}, {-1e30f, -1e30f}};
    float lrow[2][2] = {};   // per-lane partial sums (reduced in epilogue)

#pragma unroll 1
    for (int sb = 0; sb < 8; sb++) {
        asm volatile("cp.async.wait_group 1;");
        __syncthreads();

        if (sb < 6) {
            const int slot = (sb + 2) % 3;
            const int row = tid >> 3, seg = (tid & 7) * 4;
            cpa16(Ks + slot * 1152 + row * 36 + seg, kb + (sb + 2) * 1024 + tid * 4);
            cpa16(Vs + slot * 1152 + row * 36 + seg, vtb + row * 256 + (sb + 2) * 32 + seg);
        }
        asm volatile("cp.async.commit_group;");

        const float* Kb = Ks + (sb % 3) * 1152;
        const float* Vb = Vs + (sb % 3) * 1152;

        // ---- S = Q K^T for BOTH m-tiles, bias as accumulator init ----
        float s[2][4][4];
#pragma unroll
        for (int mt = 0; mt < 2; mt++) {
            const float* br0 = bb + (wb + mt * 16 + q) * 256 + sb * 32 + t * 2;
            const float* br1 = br0 + 8 * 256;
#pragma unroll
            for (int nt = 0; nt < 4; nt++) {
                float2 b0 = *(const float2*)(br0 + nt * 8);
                float2 b1 = *(const float2*)(br1 + nt * 8);
                s[mt][nt][0] = b0.x; s[mt][nt][1] = b0.y;
                s[mt][nt][2] = b1.x; s[mt][nt][3] = b1.y;
            }
        }
#pragma unroll
        for (int kc = 0; kc < 4; kc++) {
#pragma unroll
            for (int pr = 0; pr < 2; pr++) {
                unsigned kf[4];
                ldsm4(kf, Kb + (pr * 16 + (g8 >> 1) * 8 + r8) * 36 + kc * 8 + (g8 & 1) * 4);
                mma_tf32(s[0][pr * 2 + 0], qa[0][kc], &kf[0]);
                mma_tf32(s[0][pr * 2 + 1], qa[0][kc], &kf[2]);
                mma_tf32(s[1][pr * 2 + 0], qa[1][kc], &kf[0]);
                mma_tf32(s[1][pr * 2 + 1], qa[1][kc], &kf[2]);
            }
        }

        // ---- online softmax per m-tile; raw P -> warp-private smem ----
#pragma unroll
        for (int mt = 0; mt < 2; mt++) {
            float mx0 = fmaxf(fmaxf(s[mt][0][0], s[mt][0][1]), fmaxf(s[mt][1][0], s[mt][1][1]));
            float mx1 = fmaxf(fmaxf(s[mt][0][2], s[mt][0][3]), fmaxf(s[mt][1][2], s[mt][1][3]));
            mx0 = fmaxf(mx0, fmaxf(fmaxf(s[mt][2][0], s[mt][2][1]), fmaxf(s[mt][3][0], s[mt][3][1])));
            mx1 = fmaxf(mx1, fmaxf(fmaxf(s[mt][2][2], s[mt][2][3]), fmaxf(s[mt][3][2], s[mt][3][3])));
            mx0 = fmaxf(mx0, __shfl_xor_sync(0xffffffff, mx0, 1));
            mx0 = fmaxf(mx0, __shfl_xor_sync(0xffffffff, mx0, 2));
            mx1 = fmaxf(mx1, __shfl_xor_sync(0xffffffff, mx1, 1));
            mx1 = fmaxf(mx1, __shfl_xor_sync(0xffffffff, mx1, 2));
            const float mn0 = fmaxf(mrow[mt][0], mx0);
            const float mn1 = fmaxf(mrow[mt][1], mx1);
            const float cor0 = ex2(mrow[mt][0] - mn0);
            const float cor1 = ex2(mrow[mt][1] - mn1);
            mrow[mt][0] = mn0; mrow[mt][1] = mn1;
#pragma unroll
            for (int dn = 0; dn < 4; dn++) {
                o[mt][dn][0] *= cor0; o[mt][dn][1] *= cor0;
                o[mt][dn][2] *= cor1; o[mt][dn][3] *= cor1;
            }
            float sm0 = 0.f, sm1 = 0.f;
#pragma unroll
            for (int nt = 0; nt < 4; nt++) {
                float p0 = ex2(s[mt][nt][0] - mn0);
                float p1 = ex2(s[mt][nt][1] - mn0);
                float p2 = ex2(s[mt][nt][2] - mn1);
                float p3 = ex2(s[mt][nt][3] - mn1);
                sm0 += p0 + p1; sm1 += p2 + p3;
                *(float2*)&Pw[(mt * 16 + q) * 36 + nt * 8 + 2 * t] = make_float2(p0, p1);
                *(float2*)&Pw[(mt * 16 + q + 8) * 36 + nt * 8 + 2 * t] = make_float2(p2, p3);
            }
            lrow[mt][0] = lrow[mt][0] * cor0 + sm0;
            lrow[mt][1] = lrow[mt][1] * cor1 + sm1;
        }
        __syncwarp();

        // ---- O += P V : P and V fragments via ldmatrix ----
#pragma unroll
        for (int kk = 0; kk < 4; kk++) {
            unsigned pa[2][4];
            ldsm4(pa[0], Pw + ((g8 & 1) * 8 + r8) * 36 + kk * 8 + (g8 >> 1) * 4);
            ldsm4(pa[1], Pw + (16 + (g8 & 1) * 8 + r8) * 36 + kk * 8 + (g8 >> 1) * 4);
            // V tiles: vf0 covers dn 0,1 (halves via g8&1), vf1 covers dn 2,3
            unsigned vf0[4], vf1[4];
            ldsm4(vf0, Vb + (((g8 >> 1) * 8 + r8) * 36) + kk * 8 + (g8 & 1) * 4);
            ldsm4(vf1, Vb + (((2 + (g8 >> 1)) * 8 + r8) * 36) + kk * 8 + (g8 & 1) * 4);
            mma_tf32(o[0][0], pa[0], &vf0[0]);
            mma_tf32(o[0][1], pa[0], &vf0[2]);
            mma_tf32(o[0][2], pa[0], &vf1[0]);
            mma_tf32(o[0][3], pa[0], &vf1[2]);
            mma_tf32(o[1][0], pa[1], &vf0[0]);
            mma_tf32(o[1][1], pa[1], &vf0[2]);
            mma_tf32(o[1][2], pa[1], &vf1[0]);
            mma_tf32(o[1][3], pa[1], &vf1[2]);
        }
    }

    // Epilogue: reduce l partials, normalize, write (B,H,W,C) layout
    const int bimg = win >> 6, wh = (win >> 3) & 7, ww = win & 7;
#pragma unroll
    for (int mt = 0; mt < 2; mt++) {
        float l0 = lrow[mt][0], l1 = lrow[mt][1];
        l0 += __shfl_xor_sync(0xffffffff, l0, 1);
        l0 += __shfl_xor_sync(0xffffffff, l0, 2);
        l1 += __shfl_xor_sync(0xffffffff, l1, 1);
        l1 += __shfl_xor_sync(0xffffffff, l1, 2);
        const float inv0 = 1.f / l0;
        const float inv1 = 1.f / l1;
        const int tk0 = wb + mt * 16 + q;
#pragma unroll
        for (int half = 0; half < 2; half++) {
            const int tk = tk0 + half * 8;
            const float inv = half ? inv1 : inv0;
            const int gr = wh * 16 + (tk >> 4), gc = ww * 16 + (tk & 15);
            float* op = g_o + ((bimg * 128 + gr) * 128 + gc) * 256 + hd * 32;
#pragma unroll
            for (int dn = 0; dn < 4; dn++) {
                float a = o[mt][dn][half * 2] * inv;
                float b = o[mt][dn][half * 2 + 1] * inv;
                *(float2*)(op + dn * 8 + t * 2) = make_float2(a, b);
            }
        }
    }
}

// ---------------------------------------------------------------------------
extern "C" void kernel_launch(void* const* d_in, const int* in_sizes, int n_in,
                              void* d_out, int out_size) {
    (void)in_sizes; (void)n_in; (void)out_size;
    const float* x_wsa      = (const float*)d_in[0];
    const float* x_original = (const float*)d_in[1];
    const float* q_w        = (const float*)d_in[2];
    const float* q_b        = (const float*)d_in[3];
    const float* kv_w       = (const float*)d_in[4];
    const float* kv_b       = (const float*)d_in[5];
    const float* out_w      = (const float*)d_in[6];
    const float* out_b      = (const float*)d_in[7];
    const float* bias_table = (const float*)d_in[8];
    const float* rezero     = (const float*)d_in[9];
    float* out = (float*)d_out;

    cudaFuncSetAttribute(convkv_mma, cudaFuncAttributeMaxDynamicSharedMemorySize, CONV_SMEM_B);
    cudaFuncSetAttribute(gemm_mma<0>, cudaFuncAttributeMaxDynamicSharedMemorySize, GEMM_SMEM_B);
    cudaFuncSetAttribute(gemm_mma<1>, cudaFuncAttributeMaxDynamicSharedMemorySize, GEMM_SMEM_B);
    cudaFuncSetAttribute(attn_mma, cudaFuncAttributeMaxDynamicSharedMemorySize, ATT_SMEM_B);

    bias_expand<<<dim3(256, 8), 256>>>(bias_table);
    gemm_mma<0><<<dim3(512, 4), 256, GEMM_SMEM_B>>>(x_wsa, q_w, q_b, nullptr, nullptr);
    convkv_mma<<<dim3(64, 32), 256, CONV_SMEM_B>>>(x_original, kv_w, kv_b);
    attn_mma<<<dim3(256, 8), 256, ATT_SMEM_B>>>();
    gemm_mma<1><<<dim3(512, 4), 256, GEMM_SMEM_B>>>(nullptr, out_w, out_b, rezero, out);
}